// round 1
// baseline (speedup 1.0000x reference)
#include <cuda_runtime.h>
#include <cuda_bf16.h>
#include <math.h>

// ---------------- problem constants ----------------
#define BB 4
#define SS 2048
#define DD 768
#define HH 12
#define HDD 64
#define RA 32
#define RF 512
#define DFF 3072
#define ROWS (BB*SS)          // 8192

// ---------------- scratch (static device globals; no allocations) ----------------
__device__ float g_h  [ROWS*DD];
__device__ float g_q  [ROWS*DD];      // layout [B,H,S,HD]
__device__ float g_k  [ROWS*DD];
__device__ float g_v  [ROWS*DD];
__device__ float g_weff[3*DD*DD];     // [q|k|v][D][D]
__device__ float g_o  [ROWS*DD];      // [B,S,D]
__device__ float g_x1 [ROWS*DD];
__device__ float g_h2 [ROWS*DD];
__device__ float g_t1 [ROWS*RF];
__device__ float g_u  [ROWS*2*DFF];
__device__ float g_g  [ROWS*DFF];
__device__ float g_t2 [ROWS*RF];

// ---------------- layernorm: one block per row ----------------
__global__ __launch_bounds__(256) void ln_kernel(const float* __restrict__ x,
                                                 const float* __restrict__ w,
                                                 const float* __restrict__ b,
                                                 float* __restrict__ out) {
    int row = blockIdx.x;
    const float* xr = x + (size_t)row * DD;
    float vals[3];
    float s = 0.f, s2 = 0.f;
    int tid = threadIdx.x;
#pragma unroll
    for (int i = 0; i < 3; i++) {
        float v = xr[tid + i * 256];
        vals[i] = v; s += v; s2 += v * v;
    }
    __shared__ float sh[256], sh2[256];
    sh[tid] = s; sh2[tid] = s2;
    __syncthreads();
    for (int off = 128; off > 0; off >>= 1) {
        if (tid < off) { sh[tid] += sh[tid + off]; sh2[tid] += sh2[tid + off]; }
        __syncthreads();
    }
    float mean = sh[0] * (1.0f / DD);
    float var  = sh2[0] * (1.0f / DD) - mean * mean;
    float rstd = rsqrtf(var + 1e-6f);
    float* orow = out + (size_t)row * DD;
#pragma unroll
    for (int i = 0; i < 3; i++) {
        int c = tid + i * 256;
        orow[c] = (vals[i] - mean) * rstd * w[c] + b[c];
    }
}

// ---------------- effective weight: Weff[which][d][h*64+e] = sum_r U[h][d][r]*V[h][r][e] ----------------
__global__ __launch_bounds__(256) void weff_kernel(const float* __restrict__ Uq, const float* __restrict__ Vq,
                                                   const float* __restrict__ Uk, const float* __restrict__ Vk,
                                                   const float* __restrict__ Uv, const float* __restrict__ Vv,
                                                   float* __restrict__ weff) {
    int idx = blockIdx.x * 256 + threadIdx.x;
    if (idx >= 3 * DD * DD) return;
    int which = idx / (DD * DD);
    int rem = idx % (DD * DD);
    int d = rem / DD, j = rem % DD;
    int hh = j >> 6, e = j & 63;
    const float* U = (which == 0) ? Uq : (which == 1) ? Uk : Uv;
    const float* V = (which == 0) ? Vq : (which == 1) ? Vk : Vv;
    const float* Uhd = U + ((size_t)hh * DD + d) * RA;
    const float* Vh  = V + (size_t)hh * RA * HDD + e;
    float acc = 0.f;
#pragma unroll
    for (int r = 0; r < RA; r++) acc += Uhd[r] * Vh[r * HDD];
    weff[idx] = acc;
}

// ---------------- generic tiled fp32 GEMM ----------------
// C[M,N] = A[M,K] @ B (+bias) (+res). TRANSB: B is [N,K]. SCATTER: write in [B,H,S,HD].
template<bool TRANSB, bool SCATTER>
__global__ __launch_bounds__(256) void gemm_kernel(const float* __restrict__ A,
                                                   const float* __restrict__ Bm,
                                                   const float* __restrict__ bias,
                                                   const float* __restrict__ res,
                                                   float* __restrict__ C,
                                                   int M, int N, int K) {
    __shared__ float As[16 * 64];   // [k][m]
    __shared__ float Bs[16 * 64];   // [k][n]
    int tid = threadIdx.x;
    int tx = tid & 15, ty = tid >> 4;
    int m0 = blockIdx.y * 64, n0 = blockIdx.x * 64;
    float acc[4][4] = {};
    for (int k0 = 0; k0 < K; k0 += 16) {
#pragma unroll
        for (int i = 0; i < 4; i++) {
            int idx = tid + i * 256;
            int m = idx >> 4, k = idx & 15;
            As[k * 64 + m] = A[(size_t)(m0 + m) * K + k0 + k];
        }
#pragma unroll
        for (int i = 0; i < 4; i++) {
            int idx = tid + i * 256;
            if (!TRANSB) { int k = idx >> 6, n = idx & 63; Bs[k * 64 + n] = Bm[(size_t)(k0 + k) * N + n0 + n]; }
            else         { int n = idx >> 4, k = idx & 15; Bs[k * 64 + n] = Bm[(size_t)(n0 + n) * K + k0 + k]; }
        }
        __syncthreads();
#pragma unroll
        for (int k = 0; k < 16; k++) {
            float4 a = *(const float4*)&As[k * 64 + ty * 4];
            float4 bb = *(const float4*)&Bs[k * 64 + tx * 4];
            float av[4] = {a.x, a.y, a.z, a.w};
            float bv[4] = {bb.x, bb.y, bb.z, bb.w};
#pragma unroll
            for (int i = 0; i < 4; i++)
#pragma unroll
                for (int j = 0; j < 4; j++) acc[i][j] += av[i] * bv[j];
        }
        __syncthreads();
    }
#pragma unroll
    for (int i = 0; i < 4; i++) {
        int m = m0 + ty * 4 + i;
#pragma unroll
        for (int j = 0; j < 4; j++) {
            int n = n0 + tx * 4 + j;
            float v = acc[i][j];
            if (bias) v += bias[n];
            if (res)  v += res[(size_t)m * N + n];
            if (SCATTER) {
                int b = m >> 11, s = m & 2047, head = n >> 6, e = n & 63;
                C[(((size_t)b * HH + head) * SS + s) * HDD + e] = v;
            } else {
                C[(size_t)m * N + n] = v;
            }
        }
    }
}

// ---------------- RoPE (in place on q and k, layout [B,H,S,HD]) ----------------
__global__ __launch_bounds__(256) void rope_kernel(float* __restrict__ q, float* __restrict__ k,
                                                   const float* __restrict__ cosT,
                                                   const float* __restrict__ sinT) {
    int idx = blockIdx.x * 256 + threadIdx.x;   // B*H*S*32
    if (idx >= BB * HH * SS * 32) return;
    int e = idx & 31;
    int s = (idx >> 5) & 2047;
    int bh = idx >> 16;
    size_t base = ((size_t)bh * SS + s) * HDD;
    float c1 = cosT[s * HDD + e],      s1 = sinT[s * HDD + e];
    float c2 = cosT[s * HDD + e + 32], s2 = sinT[s * HDD + e + 32];
    float q1 = q[base + e], q2 = q[base + e + 32];
    q[base + e]      = q1 * c1 - q2 * s1;
    q[base + e + 32] = q2 * c2 + q1 * s2;
    float k1 = k[base + e], k2 = k[base + e + 32];
    k[base + e]      = k1 * c1 - k2 * s1;
    k[base + e + 32] = k2 * c2 + k1 * s2;
}

// ---------------- flash attention, fp32, 64x64 tiles ----------------
// grid (S/64, B*H), 256 threads. Q/K stored d-major in smem; P aliases K tile.
__global__ __launch_bounds__(256) void attn_kernel(const float* __restrict__ Q,
                                                   const float* __restrict__ K,
                                                   const float* __restrict__ V,
                                                   float* __restrict__ O) {
    __shared__ float Qt[64 * 64];   // [d][q]
    __shared__ float KP[64 * 64];   // Kt [d][kc], reused as P [q][kc]
    __shared__ float Vs[64 * 64];   // [kc][d]
    int tid = threadIdx.x;
    int tx = tid & 15, ty = tid >> 4;
    int bh = blockIdx.y;
    int q0 = blockIdx.x * 64;
    size_t bhoff = (size_t)bh * SS * HDD;

    // load Q tile, transposed to [d][q]
#pragma unroll
    for (int i = 0; i < 4; i++) {
        int idx = tid + i * 256;
        int r = idx >> 4, c4 = (idx & 15) << 2;
        float4 t = *(const float4*)&Q[bhoff + (size_t)(q0 + r) * HDD + c4];
        Qt[(c4 + 0) * 64 + r] = t.x;
        Qt[(c4 + 1) * 64 + r] = t.y;
        Qt[(c4 + 2) * 64 + r] = t.z;
        Qt[(c4 + 3) * 64 + r] = t.w;
    }

    float m_i[4], l_i[4], acc[4][4];
#pragma unroll
    for (int i = 0; i < 4; i++) {
        m_i[i] = -1e30f; l_i[i] = 0.f;
#pragma unroll
        for (int j = 0; j < 4; j++) acc[i][j] = 0.f;
    }
    const float scale = 0.125f;  // 1/sqrt(64)

    for (int kc0 = 0; kc0 < SS; kc0 += 64) {
        __syncthreads();   // previous P/V reads done
        // load K (transposed) and V (natural)
#pragma unroll
        for (int i = 0; i < 4; i++) {
            int idx = tid + i * 256;
            int r = idx >> 4, c4 = (idx & 15) << 2;
            float4 t = *(const float4*)&K[bhoff + (size_t)(kc0 + r) * HDD + c4];
            KP[(c4 + 0) * 64 + r] = t.x;
            KP[(c4 + 1) * 64 + r] = t.y;
            KP[(c4 + 2) * 64 + r] = t.z;
            KP[(c4 + 3) * 64 + r] = t.w;
            float4 tv = *(const float4*)&V[bhoff + (size_t)(kc0 + r) * HDD + c4];
            *(float4*)&Vs[r * 64 + c4] = tv;
        }
        __syncthreads();

        // scores: sc[i][j] = Q[q=ty*4+i] . K[kc=tx*4+j]
        float sc[4][4] = {};
#pragma unroll
        for (int d = 0; d < 64; d++) {
            float4 a = *(const float4*)&Qt[d * 64 + ty * 4];
            float4 b = *(const float4*)&KP[d * 64 + tx * 4];
            float av[4] = {a.x, a.y, a.z, a.w};
            float bv[4] = {b.x, b.y, b.z, b.w};
#pragma unroll
            for (int i = 0; i < 4; i++)
#pragma unroll
                for (int j = 0; j < 4; j++) sc[i][j] += av[i] * bv[j];
        }
        float corr[4];
#pragma unroll
        for (int i = 0; i < 4; i++) {
#pragma unroll
            for (int j = 0; j < 4; j++) sc[i][j] *= scale;
            float rm = fmaxf(fmaxf(sc[i][0], sc[i][1]), fmaxf(sc[i][2], sc[i][3]));
#pragma unroll
            for (int off = 1; off < 16; off <<= 1)
                rm = fmaxf(rm, __shfl_xor_sync(0xffffffffu, rm, off));
            float mn = fmaxf(m_i[i], rm);
            corr[i] = __expf(m_i[i] - mn);
            m_i[i] = mn;
            float rs = 0.f;
#pragma unroll
            for (int j = 0; j < 4; j++) { float p = __expf(sc[i][j] - mn); sc[i][j] = p; rs += p; }
#pragma unroll
            for (int off = 1; off < 16; off <<= 1)
                rs += __shfl_xor_sync(0xffffffffu, rs, off);
            l_i[i] = l_i[i] * corr[i] + rs;
        }
        __syncthreads();   // all Kt reads done before overwrite as P
#pragma unroll
        for (int i = 0; i < 4; i++)
#pragma unroll
            for (int j = 0; j < 4; j++) KP[(ty * 4 + i) * 64 + tx * 4 + j] = sc[i][j];
        __syncthreads();

        // O update: acc[i][j] = acc*corr + sum_kc P[q][kc] * V[kc][d=tx*4+j]
#pragma unroll
        for (int i = 0; i < 4; i++)
#pragma unroll
            for (int j = 0; j < 4; j++) acc[i][j] *= corr[i];
#pragma unroll
        for (int kc = 0; kc < 64; kc++) {
            float4 vb = *(const float4*)&Vs[kc * 64 + tx * 4];
            float vv[4] = {vb.x, vb.y, vb.z, vb.w};
            float pv[4];
#pragma unroll
            for (int i = 0; i < 4; i++) pv[i] = KP[(ty * 4 + i) * 64 + kc];
#pragma unroll
            for (int i = 0; i < 4; i++)
#pragma unroll
                for (int j = 0; j < 4; j++) acc[i][j] += pv[i] * vv[j];
        }
    }

    // write O into [B, S, D]
    int b = bh / HH, hd = bh % HH;
#pragma unroll
    for (int i = 0; i < 4; i++) {
        float inv = 1.0f / l_i[i];
        int qrow = q0 + ty * 4 + i;
        size_t base = ((size_t)(b * SS + qrow)) * DD + hd * HDD + tx * 4;
#pragma unroll
        for (int j = 0; j < 4; j++) O[base + j] = acc[i][j] * inv;
    }
}

// ---------------- GEGLU ----------------
__global__ __launch_bounds__(256) void geglu_kernel(const float* __restrict__ u, float* __restrict__ g) {
    int idx = blockIdx.x * 256 + threadIdx.x;
    if (idx >= ROWS * DFF) return;
    int row = idx / DFF, col = idx % DFF;
    float x1 = u[(size_t)row * (2 * DFF) + col];
    float x2 = u[(size_t)row * (2 * DFF) + DFF + col];
    float t = 0.7978845608028654f * (x1 + 0.044715f * x1 * x1 * x1);
    float ge = 0.5f * x1 * (1.0f + tanhf(t));
    g[idx] = ge * x2;
}

// ---------------- launch ----------------
extern "C" void kernel_launch(void* const* d_in, const int* in_sizes, int n_in,
                              void* d_out, int out_size) {
    const float* x    = (const float*)d_in[0];
    const float* anw  = (const float*)d_in[1];
    const float* anb  = (const float*)d_in[2];
    const float* Uq   = (const float*)d_in[3];
    const float* Vq   = (const float*)d_in[4];
    const float* bq   = (const float*)d_in[5];
    const float* Uk   = (const float*)d_in[6];
    const float* Vk   = (const float*)d_in[7];
    const float* bk   = (const float*)d_in[8];
    const float* Uv   = (const float*)d_in[9];
    const float* Vv   = (const float*)d_in[10];
    const float* bv   = (const float*)d_in[11];
    const float* Wo_w = (const float*)d_in[12];
    const float* Wo_b = (const float*)d_in[13];
    const float* mnw  = (const float*)d_in[14];
    const float* mnb  = (const float*)d_in[15];
    const float* Ui   = (const float*)d_in[16];
    const float* Vi   = (const float*)d_in[17];
    const float* bi   = (const float*)d_in[18];
    const float* Uo   = (const float*)d_in[19];
    const float* Vo   = (const float*)d_in[20];
    const float* bo   = (const float*)d_in[21];
    const float* cosT = (const float*)d_in[22];
    const float* sinT = (const float*)d_in[23];
    float* out = (float*)d_out;

    float *h, *q, *k, *v, *weff, *o, *x1, *h2, *t1, *u, *g, *t2;
    cudaGetSymbolAddress((void**)&h,  g_h);
    cudaGetSymbolAddress((void**)&q,  g_q);
    cudaGetSymbolAddress((void**)&k,  g_k);
    cudaGetSymbolAddress((void**)&v,  g_v);
    cudaGetSymbolAddress((void**)&weff, g_weff);
    cudaGetSymbolAddress((void**)&o,  g_o);
    cudaGetSymbolAddress((void**)&x1, g_x1);
    cudaGetSymbolAddress((void**)&h2, g_h2);
    cudaGetSymbolAddress((void**)&t1, g_t1);
    cudaGetSymbolAddress((void**)&u,  g_u);
    cudaGetSymbolAddress((void**)&g,  g_g);
    cudaGetSymbolAddress((void**)&t2, g_t2);

    // 1. LN1
    ln_kernel<<<ROWS, 256>>>(x, anw, anb, h);
    // 2. effective per-head projection weights
    weff_kernel<<<(3 * DD * DD + 255) / 256, 256>>>(Uq, Vq, Uk, Vk, Uv, Vv, weff);
    // 3. Q/K/V projections (scatter into [B,H,S,HD])
    dim3 gQKV(DD / 64, ROWS / 64);
    gemm_kernel<false, true><<<gQKV, 256>>>(h, weff,                 bq, nullptr, q, ROWS, DD, DD);
    gemm_kernel<false, true><<<gQKV, 256>>>(h, weff + DD * DD,       bk, nullptr, k, ROWS, DD, DD);
    gemm_kernel<false, true><<<gQKV, 256>>>(h, weff + 2 * DD * DD,   bv, nullptr, v, ROWS, DD, DD);
    // 4. RoPE on q,k
    rope_kernel<<<(BB * HH * SS * 32 + 255) / 256, 256>>>(q, k, cosT, sinT);
    // 5. attention
    attn_kernel<<<dim3(SS / 64, BB * HH), 256>>>(q, k, v, o);
    // 6. x1 = x + o @ Wo^T + Wo_b
    gemm_kernel<true, false><<<dim3(DD / 64, ROWS / 64), 256>>>(o, Wo_w, Wo_b, x, x1, ROWS, DD, DD);
    // 7. LN2
    ln_kernel<<<ROWS, 256>>>(x1, mnw, mnb, h2);
    // 8. t1 = h2 @ Ui
    gemm_kernel<false, false><<<dim3(RF / 64, ROWS / 64), 256>>>(h2, Ui, nullptr, nullptr, t1, ROWS, RF, DD);
    // 9. u = t1 @ Vi + bi
    gemm_kernel<false, false><<<dim3(2 * DFF / 64, ROWS / 64), 256>>>(t1, Vi, bi, nullptr, u, ROWS, 2 * DFF, RF);
    // 10. GEGLU
    geglu_kernel<<<(ROWS * DFF + 255) / 256, 256>>>(u, g);
    // 11. t2 = g @ Uo
    gemm_kernel<false, false><<<dim3(RF / 64, ROWS / 64), 256>>>(g, Uo, nullptr, nullptr, t2, ROWS, RF, DFF);
    // 12. out = x1 + t2 @ Vo + bo
    gemm_kernel<false, false><<<dim3(DD / 64, ROWS / 64), 256>>>(t2, Vo, bo, x1, out, ROWS, DD, RF);
}

// round 2
// speedup vs baseline: 1.5391x; 1.5391x over previous
#include <cuda_runtime.h>
#include <cuda_bf16.h>
#include <math.h>

// ---------------- problem constants ----------------
#define BB 4
#define SS 2048
#define DD 768
#define HH 12
#define HDD 64
#define RA 32
#define RF 512
#define DFF 3072
#define ROWS (BB*SS)          // 8192

// ---------------- scratch (static device globals; no allocations) ----------------
__device__ float g_h  [ROWS*DD];
__device__ float g_q  [ROWS*DD];      // layout [B,H,S,HD]
__device__ float g_k  [ROWS*DD];
__device__ float g_v  [ROWS*DD];
__device__ float g_weff[3*DD*DD];     // [q|k|v][D][D]
__device__ float g_o  [ROWS*DD];      // [B,S,D]
__device__ float g_x1 [ROWS*DD];
__device__ float g_h2 [ROWS*DD];
__device__ float g_t1 [ROWS*RF];
__device__ float g_u  [ROWS*2*DFF];
__device__ float g_g  [ROWS*DFF];
__device__ float g_t2 [ROWS*RF];

// ---------------- layernorm: one block per row ----------------
__global__ __launch_bounds__(256) void ln_kernel(const float* __restrict__ x,
                                                 const float* __restrict__ w,
                                                 const float* __restrict__ b,
                                                 float* __restrict__ out) {
    int row = blockIdx.x;
    const float* xr = x + (size_t)row * DD;
    float vals[3];
    float s = 0.f, s2 = 0.f;
    int tid = threadIdx.x;
#pragma unroll
    for (int i = 0; i < 3; i++) {
        float v = xr[tid + i * 256];
        vals[i] = v; s += v; s2 += v * v;
    }
    __shared__ float sh[256], sh2[256];
    sh[tid] = s; sh2[tid] = s2;
    __syncthreads();
    for (int off = 128; off > 0; off >>= 1) {
        if (tid < off) { sh[tid] += sh[tid + off]; sh2[tid] += sh2[tid + off]; }
        __syncthreads();
    }
    float mean = sh[0] * (1.0f / DD);
    float var  = sh2[0] * (1.0f / DD) - mean * mean;
    float rstd = rsqrtf(var + 1e-6f);
    float* orow = out + (size_t)row * DD;
#pragma unroll
    for (int i = 0; i < 3; i++) {
        int c = tid + i * 256;
        orow[c] = (vals[i] - mean) * rstd * w[c] + b[c];
    }
}

// ---------------- effective weight ----------------
__global__ __launch_bounds__(256) void weff_kernel(const float* __restrict__ Uq, const float* __restrict__ Vq,
                                                   const float* __restrict__ Uk, const float* __restrict__ Vk,
                                                   const float* __restrict__ Uv, const float* __restrict__ Vv,
                                                   float* __restrict__ weff) {
    int idx = blockIdx.x * 256 + threadIdx.x;
    if (idx >= 3 * DD * DD) return;
    int which = idx / (DD * DD);
    int rem = idx % (DD * DD);
    int d = rem / DD, j = rem % DD;
    int hh = j >> 6, e = j & 63;
    const float* U = (which == 0) ? Uq : (which == 1) ? Uk : Uv;
    const float* V = (which == 0) ? Vq : (which == 1) ? Vk : Vv;
    const float* Uhd = U + ((size_t)hh * DD + d) * RA;
    const float* Vh  = V + (size_t)hh * RA * HDD + e;
    float acc = 0.f;
#pragma unroll
    for (int r = 0; r < RA; r++) acc += Uhd[r] * Vh[r * HDD];
    weff[idx] = acc;
}

// ---------------- 128x128x16 fp32 GEMM, 8x8 microtile, double-buffered ----------------
// C[M,N] = A[M,K] @ B (+bias) (+res). TRANSB: B is [N,K]. SCATTER: write [B,H,S,HD].
template<bool TRANSB, bool SCATTER>
__global__ __launch_bounds__(256, 2) void gemm128(const float* __restrict__ A,
                                                  const float* __restrict__ Bm,
                                                  const float* __restrict__ bias,
                                                  const float* __restrict__ res,
                                                  float* __restrict__ C,
                                                  int M, int N, int K) {
    __shared__ float As[2][16][128];
    __shared__ float Bs[2][16][128];
    int tid = threadIdx.x;
    int tx = tid & 15, ty = tid >> 4;
    int m0 = blockIdx.y * 128, n0 = blockIdx.x * 128;

    // A load mapping: each thread loads rows (arow, arow+64), 4 contiguous k
    int arow = tid >> 2;            // 0..63
    int akq  = (tid & 3) << 2;      // 0,4,8,12
    const float* Ap0 = A + (size_t)(m0 + arow) * K + akq;
    const float* Ap1 = A + (size_t)(m0 + arow + 64) * K + akq;
    // B load mapping
    int brow = tid >> 5;            // 0..7 (non-trans)
    int bnq  = (tid & 31) << 2;     // 0..124
    const float* Bp0;
    const float* Bp1;
    if (TRANSB) {
        Bp0 = Bm + (size_t)(n0 + arow) * K + akq;
        Bp1 = Bm + (size_t)(n0 + arow + 64) * K + akq;
    } else {
        Bp0 = Bm + (size_t)brow * N + n0 + bnq;
        Bp1 = Bm + (size_t)(brow + 8) * N + n0 + bnq;
    }

    float acc[8][8];
#pragma unroll
    for (int i = 0; i < 8; i++)
#pragma unroll
        for (int j = 0; j < 8; j++) acc[i][j] = 0.f;

    int nch = K >> 4;
    float4 ra0, ra1, rb0, rb1;

    // prologue: load chunk 0
    ra0 = *(const float4*)(Ap0);
    ra1 = *(const float4*)(Ap1);
    if (TRANSB) { rb0 = *(const float4*)(Bp0); rb1 = *(const float4*)(Bp1); }
    else        { rb0 = *(const float4*)(Bp0); rb1 = *(const float4*)(Bp1); }
    {
        As[0][akq + 0][arow] = ra0.x; As[0][akq + 1][arow] = ra0.y;
        As[0][akq + 2][arow] = ra0.z; As[0][akq + 3][arow] = ra0.w;
        As[0][akq + 0][arow + 64] = ra1.x; As[0][akq + 1][arow + 64] = ra1.y;
        As[0][akq + 2][arow + 64] = ra1.z; As[0][akq + 3][arow + 64] = ra1.w;
        if (TRANSB) {
            Bs[0][akq + 0][arow] = rb0.x; Bs[0][akq + 1][arow] = rb0.y;
            Bs[0][akq + 2][arow] = rb0.z; Bs[0][akq + 3][arow] = rb0.w;
            Bs[0][akq + 0][arow + 64] = rb1.x; Bs[0][akq + 1][arow + 64] = rb1.y;
            Bs[0][akq + 2][arow + 64] = rb1.z; Bs[0][akq + 3][arow + 64] = rb1.w;
        } else {
            *(float4*)&Bs[0][brow][bnq] = rb0;
            *(float4*)&Bs[0][brow + 8][bnq] = rb1;
        }
    }
    __syncthreads();

    int p = 0;
    for (int c = 0; c < nch; c++) {
        if (c + 1 < nch) {
            int k0 = (c + 1) << 4;
            ra0 = *(const float4*)(Ap0 + k0);
            ra1 = *(const float4*)(Ap1 + k0);
            if (TRANSB) { rb0 = *(const float4*)(Bp0 + k0); rb1 = *(const float4*)(Bp1 + k0); }
            else        { rb0 = *(const float4*)(Bp0 + (size_t)k0 * N); rb1 = *(const float4*)(Bp1 + (size_t)k0 * N); }
        }
#pragma unroll
        for (int k = 0; k < 16; k++) {
            float4 a0 = *(const float4*)&As[p][k][ty * 4];
            float4 a1 = *(const float4*)&As[p][k][64 + ty * 4];
            float4 b0 = *(const float4*)&Bs[p][k][tx * 4];
            float4 b1 = *(const float4*)&Bs[p][k][64 + tx * 4];
            float av[8] = {a0.x, a0.y, a0.z, a0.w, a1.x, a1.y, a1.z, a1.w};
            float bv[8] = {b0.x, b0.y, b0.z, b0.w, b1.x, b1.y, b1.z, b1.w};
#pragma unroll
            for (int i = 0; i < 8; i++)
#pragma unroll
                for (int j = 0; j < 8; j++) acc[i][j] += av[i] * bv[j];
        }
        if (c + 1 < nch) {
            int q = p ^ 1;
            As[q][akq + 0][arow] = ra0.x; As[q][akq + 1][arow] = ra0.y;
            As[q][akq + 2][arow] = ra0.z; As[q][akq + 3][arow] = ra0.w;
            As[q][akq + 0][arow + 64] = ra1.x; As[q][akq + 1][arow + 64] = ra1.y;
            As[q][akq + 2][arow + 64] = ra1.z; As[q][akq + 3][arow + 64] = ra1.w;
            if (TRANSB) {
                Bs[q][akq + 0][arow] = rb0.x; Bs[q][akq + 1][arow] = rb0.y;
                Bs[q][akq + 2][arow] = rb0.z; Bs[q][akq + 3][arow] = rb0.w;
                Bs[q][akq + 0][arow + 64] = rb1.x; Bs[q][akq + 1][arow + 64] = rb1.y;
                Bs[q][akq + 2][arow + 64] = rb1.z; Bs[q][akq + 3][arow + 64] = rb1.w;
            } else {
                *(float4*)&Bs[q][brow][bnq] = rb0;
                *(float4*)&Bs[q][brow + 8][bnq] = rb1;
            }
            __syncthreads();
            p = q;
        }
    }

    // epilogue
#pragma unroll
    for (int ih = 0; ih < 2; ih++) {
#pragma unroll
        for (int i = 0; i < 4; i++) {
            int m = m0 + ih * 64 + ty * 4 + i;
#pragma unroll
            for (int jh = 0; jh < 2; jh++) {
                int n = n0 + jh * 64 + tx * 4;
                float4 v;
                v.x = acc[ih * 4 + i][jh * 4 + 0];
                v.y = acc[ih * 4 + i][jh * 4 + 1];
                v.z = acc[ih * 4 + i][jh * 4 + 2];
                v.w = acc[ih * 4 + i][jh * 4 + 3];
                if (bias) {
                    float4 bb = *(const float4*)&bias[n];
                    v.x += bb.x; v.y += bb.y; v.z += bb.z; v.w += bb.w;
                }
                if (res) {
                    float4 rr = *(const float4*)&res[(size_t)m * N + n];
                    v.x += rr.x; v.y += rr.y; v.z += rr.z; v.w += rr.w;
                }
                if (SCATTER) {
                    int b = m >> 11, s = m & 2047, head = n >> 6, e = n & 63;
                    *(float4*)&C[(((size_t)b * HH + head) * SS + s) * HDD + e] = v;
                } else {
                    *(float4*)&C[(size_t)m * N + n] = v;
                }
            }
        }
    }
}

// ---------------- RoPE (in place on q and k, layout [B,H,S,HD]) ----------------
__global__ __launch_bounds__(256) void rope_kernel(float* __restrict__ q, float* __restrict__ k,
                                                   const float* __restrict__ cosT,
                                                   const float* __restrict__ sinT) {
    int idx = blockIdx.x * 256 + threadIdx.x;   // B*H*S*32
    if (idx >= BB * HH * SS * 32) return;
    int e = idx & 31;
    int s = (idx >> 5) & 2047;
    int bh = idx >> 16;
    size_t base = ((size_t)bh * SS + s) * HDD;
    float c1 = cosT[s * HDD + e],      s1 = sinT[s * HDD + e];
    float c2 = cosT[s * HDD + e + 32], s2 = sinT[s * HDD + e + 32];
    float q1 = q[base + e], q2 = q[base + e + 32];
    q[base + e]      = q1 * c1 - q2 * s1;
    q[base + e + 32] = q2 * c2 + q1 * s2;
    float k1 = k[base + e], k2 = k[base + e + 32];
    k[base + e]      = k1 * c1 - k2 * s1;
    k[base + e + 32] = k2 * c2 + k1 * s2;
}

// ---------------- flash attention fp32, 128q x 64kc tiles, 8-row microtile ----------------
// smem: Qt[64][128] d-major | Kt[64][64] d-major | Vs[64][64] natural | P[128][65]
#define P_STRIDE 65
#define ATTN_SMEM_FLOATS (64*128 + 64*64 + 64*64 + 128*P_STRIDE)
__global__ __launch_bounds__(256, 2) void attn2(const float* __restrict__ Q,
                                                const float* __restrict__ K,
                                                const float* __restrict__ V,
                                                float* __restrict__ O) {
    extern __shared__ float sm[];
    float* Qt = sm;                       // [d][q] stride 128
    float* Kt = sm + 64 * 128;            // [d][kc] stride 64
    float* Vs = Kt + 64 * 64;             // [kc][d] stride 64
    float* Ps = Vs + 64 * 64;             // [q][kc] stride 65

    int tid = threadIdx.x;
    int tx = tid & 15, ty = tid >> 4;
    int bh = blockIdx.y;
    int q0 = blockIdx.x * 128;
    size_t bhoff = (size_t)bh * SS * HDD;

    // load Q tile transposed into Qt[d][q]
#pragma unroll
    for (int i = 0; i < 8; i++) {
        int idx = tid + i * 256;
        int r = idx >> 4, c4 = (idx & 15) << 2;
        float4 t = *(const float4*)&Q[bhoff + (size_t)(q0 + r) * HDD + c4];
        Qt[(c4 + 0) * 128 + r] = t.x;
        Qt[(c4 + 1) * 128 + r] = t.y;
        Qt[(c4 + 2) * 128 + r] = t.z;
        Qt[(c4 + 3) * 128 + r] = t.w;
    }

    float m_i[8], l_i[8], acc[8][4];
#pragma unroll
    for (int i = 0; i < 8; i++) {
        m_i[i] = -1e30f; l_i[i] = 0.f;
#pragma unroll
        for (int j = 0; j < 4; j++) acc[i][j] = 0.f;
    }
    const float scale = 0.125f;

    for (int kc0 = 0; kc0 < SS; kc0 += 64) {
        __syncthreads();   // prior P/V reads done, Qt ready (first iter)
        // load K transposed, V natural
#pragma unroll
        for (int i = 0; i < 4; i++) {
            int idx = tid + i * 256;
            int r = idx >> 4, c4 = (idx & 15) << 2;
            float4 t = *(const float4*)&K[bhoff + (size_t)(kc0 + r) * HDD + c4];
            Kt[(c4 + 0) * 64 + r] = t.x;
            Kt[(c4 + 1) * 64 + r] = t.y;
            Kt[(c4 + 2) * 64 + r] = t.z;
            Kt[(c4 + 3) * 64 + r] = t.w;
            float4 tv = *(const float4*)&V[bhoff + (size_t)(kc0 + r) * HDD + c4];
            *(float4*)&Vs[r * 64 + c4] = tv;
        }
        __syncthreads();

        // scores sc[i][j]: q rows {ty*4+i | i<4} and {64+ty*4+(i-4)}, kc = tx*4+j
        float sc[8][4];
#pragma unroll
        for (int i = 0; i < 8; i++)
#pragma unroll
            for (int j = 0; j < 4; j++) sc[i][j] = 0.f;
#pragma unroll
        for (int d = 0; d < 64; d++) {
            float4 a0 = *(const float4*)&Qt[d * 128 + ty * 4];
            float4 a1 = *(const float4*)&Qt[d * 128 + 64 + ty * 4];
            float4 b  = *(const float4*)&Kt[d * 64 + tx * 4];
            float av[8] = {a0.x, a0.y, a0.z, a0.w, a1.x, a1.y, a1.z, a1.w};
            float bv[4] = {b.x, b.y, b.z, b.w};
#pragma unroll
            for (int i = 0; i < 8; i++)
#pragma unroll
                for (int j = 0; j < 4; j++) sc[i][j] += av[i] * bv[j];
        }

        float corr[8];
#pragma unroll
        for (int i = 0; i < 8; i++) {
#pragma unroll
            for (int j = 0; j < 4; j++) sc[i][j] *= scale;
            float rm = fmaxf(fmaxf(sc[i][0], sc[i][1]), fmaxf(sc[i][2], sc[i][3]));
#pragma unroll
            for (int off = 1; off < 16; off <<= 1)
                rm = fmaxf(rm, __shfl_xor_sync(0xffffffffu, rm, off));
            float mn = fmaxf(m_i[i], rm);
            corr[i] = __expf(m_i[i] - mn);
            m_i[i] = mn;
            float rs = 0.f;
#pragma unroll
            for (int j = 0; j < 4; j++) { float pp = __expf(sc[i][j] - mn); sc[i][j] = pp; rs += pp; }
#pragma unroll
            for (int off = 1; off < 16; off <<= 1)
                rs += __shfl_xor_sync(0xffffffffu, rs, off);
            l_i[i] = l_i[i] * corr[i] + rs;
        }

        // store P (stride 65 => conflict-free column reads)
#pragma unroll
        for (int i = 0; i < 8; i++) {
            int qrow = (i < 4) ? (ty * 4 + i) : (64 + ty * 4 + i - 4);
#pragma unroll
            for (int j = 0; j < 4; j++) Ps[qrow * P_STRIDE + tx * 4 + j] = sc[i][j];
        }
        __syncthreads();

        // O update
#pragma unroll
        for (int i = 0; i < 8; i++)
#pragma unroll
            for (int j = 0; j < 4; j++) acc[i][j] *= corr[i];
#pragma unroll
        for (int kc = 0; kc < 64; kc++) {
            float4 vb = *(const float4*)&Vs[kc * 64 + tx * 4];
            float vv[4] = {vb.x, vb.y, vb.z, vb.w};
            float pv[8];
#pragma unroll
            for (int i = 0; i < 8; i++) {
                int qrow = (i < 4) ? (ty * 4 + i) : (64 + ty * 4 + i - 4);
                pv[i] = Ps[qrow * P_STRIDE + kc];
            }
#pragma unroll
            for (int i = 0; i < 8; i++)
#pragma unroll
                for (int j = 0; j < 4; j++) acc[i][j] += pv[i] * vv[j];
        }
    }

    // write O into [B,S,D]
    int b = bh / HH, hd = bh % HH;
#pragma unroll
    for (int i = 0; i < 8; i++) {
        float inv = 1.0f / l_i[i];
        int qrow = q0 + ((i < 4) ? (ty * 4 + i) : (64 + ty * 4 + i - 4));
        size_t base = ((size_t)(b * SS + qrow)) * DD + hd * HDD + tx * 4;
        float4 v;
        v.x = acc[i][0] * inv; v.y = acc[i][1] * inv;
        v.z = acc[i][2] * inv; v.w = acc[i][3] * inv;
        *(float4*)&O[base] = v;
    }
}

// ---------------- GEGLU ----------------
__global__ __launch_bounds__(256) void geglu_kernel(const float* __restrict__ u, float* __restrict__ g) {
    int idx = blockIdx.x * 256 + threadIdx.x;
    if (idx >= ROWS * DFF) return;
    int row = idx / DFF, col = idx % DFF;
    float x1 = u[(size_t)row * (2 * DFF) + col];
    float x2 = u[(size_t)row * (2 * DFF) + DFF + col];
    float t = 0.7978845608028654f * (x1 + 0.044715f * x1 * x1 * x1);
    float ge = 0.5f * x1 * (1.0f + tanhf(t));
    g[idx] = ge * x2;
}

// ---------------- launch ----------------
extern "C" void kernel_launch(void* const* d_in, const int* in_sizes, int n_in,
                              void* d_out, int out_size) {
    const float* x    = (const float*)d_in[0];
    const float* anw  = (const float*)d_in[1];
    const float* anb  = (const float*)d_in[2];
    const float* Uq   = (const float*)d_in[3];
    const float* Vq   = (const float*)d_in[4];
    const float* bq   = (const float*)d_in[5];
    const float* Uk   = (const float*)d_in[6];
    const float* Vk   = (const float*)d_in[7];
    const float* bk   = (const float*)d_in[8];
    const float* Uv   = (const float*)d_in[9];
    const float* Vv   = (const float*)d_in[10];
    const float* bv   = (const float*)d_in[11];
    const float* Wo_w = (const float*)d_in[12];
    const float* Wo_b = (const float*)d_in[13];
    const float* mnw  = (const float*)d_in[14];
    const float* mnb  = (const float*)d_in[15];
    const float* Ui   = (const float*)d_in[16];
    const float* Vi   = (const float*)d_in[17];
    const float* bi   = (const float*)d_in[18];
    const float* Uo   = (const float*)d_in[19];
    const float* Vo   = (const float*)d_in[20];
    const float* bo   = (const float*)d_in[21];
    const float* cosT = (const float*)d_in[22];
    const float* sinT = (const float*)d_in[23];
    float* out = (float*)d_out;

    float *h, *q, *k, *v, *weff, *o, *x1, *h2, *t1, *u, *g, *t2;
    cudaGetSymbolAddress((void**)&h,  g_h);
    cudaGetSymbolAddress((void**)&q,  g_q);
    cudaGetSymbolAddress((void**)&k,  g_k);
    cudaGetSymbolAddress((void**)&v,  g_v);
    cudaGetSymbolAddress((void**)&weff, g_weff);
    cudaGetSymbolAddress((void**)&o,  g_o);
    cudaGetSymbolAddress((void**)&x1, g_x1);
    cudaGetSymbolAddress((void**)&h2, g_h2);
    cudaGetSymbolAddress((void**)&t1, g_t1);
    cudaGetSymbolAddress((void**)&u,  g_u);
    cudaGetSymbolAddress((void**)&g,  g_g);
    cudaGetSymbolAddress((void**)&t2, g_t2);

    const int attn_smem = ATTN_SMEM_FLOATS * 4;  // 98816 bytes
    cudaFuncSetAttribute(attn2, cudaFuncAttributeMaxDynamicSharedMemorySize, attn_smem);

    // 1. LN1
    ln_kernel<<<ROWS, 256>>>(x, anw, anb, h);
    // 2. effective per-head projection weights
    weff_kernel<<<(3 * DD * DD + 255) / 256, 256>>>(Uq, Vq, Uk, Vk, Uv, Vv, weff);
    // 3. Q/K/V projections (scatter into [B,H,S,HD])
    dim3 gQKV(DD / 128, ROWS / 128);
    gemm128<false, true><<<gQKV, 256>>>(h, weff,               bq, nullptr, q, ROWS, DD, DD);
    gemm128<false, true><<<gQKV, 256>>>(h, weff + DD * DD,     bk, nullptr, k, ROWS, DD, DD);
    gemm128<false, true><<<gQKV, 256>>>(h, weff + 2 * DD * DD, bv, nullptr, v, ROWS, DD, DD);
    // 4. RoPE on q,k
    rope_kernel<<<(BB * HH * SS * 32 + 255) / 256, 256>>>(q, k, cosT, sinT);
    // 5. attention
    attn2<<<dim3(SS / 128, BB * HH), 256, attn_smem>>>(q, k, v, o);
    // 6. x1 = x + o @ Wo^T + Wo_b
    gemm128<true, false><<<dim3(DD / 128, ROWS / 128), 256>>>(o, Wo_w, Wo_b, x, x1, ROWS, DD, DD);
    // 7. LN2
    ln_kernel<<<ROWS, 256>>>(x1, mnw, mnb, h2);
    // 8. t1 = h2 @ Ui
    gemm128<false, false><<<dim3(RF / 128, ROWS / 128), 256>>>(h2, Ui, nullptr, nullptr, t1, ROWS, RF, DD);
    // 9. u = t1 @ Vi + bi
    gemm128<false, false><<<dim3(2 * DFF / 128, ROWS / 128), 256>>>(t1, Vi, bi, nullptr, u, ROWS, 2 * DFF, RF);
    // 10. GEGLU
    geglu_kernel<<<(ROWS * DFF + 255) / 256, 256>>>(u, g);
    // 11. t2 = g @ Uo
    gemm128<false, false><<<dim3(RF / 128, ROWS / 128), 256>>>(g, Uo, nullptr, nullptr, t2, ROWS, RF, DFF);
    // 12. out = x1 + t2 @ Vo + bo
    gemm128<false, false><<<dim3(DD / 128, ROWS / 128), 256>>>(t2, Vo, bo, x1, out, ROWS, DD, RF);
}

// round 4
// speedup vs baseline: 2.0149x; 1.3092x over previous
#include <cuda_runtime.h>
#include <cuda_bf16.h>
#include <cuda_pipeline.h>
#include <mma.h>
#include <math.h>

using namespace nvcuda;

// ---------------- problem constants ----------------
#define BB 4
#define SS 2048
#define DD 768
#define HH 12
#define HDD 64
#define RA 32
#define RF 512
#define DFF 3072
#define ROWS (BB*SS)          // 8192

// ---------------- GEMM tile constants ----------------
#define BK 32
#define LDAs 48               // bf16 elems, 96B rows (16B aligned)
#define LDBs 136              // bf16 elems, 272B rows (16B aligned)
#define A_TILE (128*LDAs)     // 6144
#define B_TILE (BK*LDBs)      // 4352
#define STAGE (2*A_TILE + 2*B_TILE)   // 20992 bf16 elems
#define GEMM_SMEM (2*STAGE*2)         // 83968 bytes
#define LDC 132

typedef __nv_bfloat16 bf16;

// ---------------- scratch (static device globals; no allocations) ----------------
__device__ bf16  g_hh [ROWS*DD];
__device__ bf16  g_hl [ROWS*DD];
__device__ bf16  g_weffh[3*DD*DD];
__device__ bf16  g_weffl[3*DD*DD];
__device__ bf16  g_woth[DD*DD];
__device__ bf16  g_wotl[DD*DD];
__device__ bf16  g_uih[DD*RF],  g_uil[DD*RF];
__device__ bf16  g_vih[RF*2*DFF], g_vil[RF*2*DFF];
__device__ bf16  g_uoh[DFF*RF], g_uol[DFF*RF];
__device__ bf16  g_voh[RF*DD],  g_vol[RF*DD];
__device__ float g_q  [ROWS*DD];      // [B,H,S,HD]
__device__ float g_k  [ROWS*DD];
__device__ float g_v  [ROWS*DD];
__device__ bf16  g_oh [ROWS*DD];      // [B,S,D] hi/lo
__device__ bf16  g_ol [ROWS*DD];
__device__ float g_x1 [ROWS*DD];
__device__ bf16  g_h2h[ROWS*DD];
__device__ bf16  g_h2l[ROWS*DD];
__device__ bf16  g_t1h[ROWS*RF], g_t1l[ROWS*RF];
__device__ float g_u  [ROWS*2*DFF];
__device__ bf16  g_gh [ROWS*DFF], g_gl[ROWS*DFF];
__device__ bf16  g_t2h[ROWS*RF], g_t2l[ROWS*RF];

__device__ __forceinline__ void bsplit(float a, bf16& h, bf16& l) {
    h = __float2bfloat16(a);
    l = __float2bfloat16(a - __bfloat162float(h));
}

// ---------------- layernorm -> bf16 hi/lo planes ----------------
__global__ __launch_bounds__(256) void ln_split(const float* __restrict__ x,
                                                const float* __restrict__ w,
                                                const float* __restrict__ b,
                                                bf16* __restrict__ oh,
                                                bf16* __restrict__ ol) {
    int row = blockIdx.x;
    const float* xr = x + (size_t)row * DD;
    float vals[3];
    float s = 0.f, s2 = 0.f;
    int tid = threadIdx.x;
#pragma unroll
    for (int i = 0; i < 3; i++) {
        float v = xr[tid + i * 256];
        vals[i] = v; s += v; s2 += v * v;
    }
    __shared__ float sh[256], sh2[256];
    sh[tid] = s; sh2[tid] = s2;
    __syncthreads();
    for (int off = 128; off > 0; off >>= 1) {
        if (tid < off) { sh[tid] += sh[tid + off]; sh2[tid] += sh2[tid + off]; }
        __syncthreads();
    }
    float mean = sh[0] * (1.0f / DD);
    float var  = sh2[0] * (1.0f / DD) - mean * mean;
    float rstd = rsqrtf(var + 1e-6f);
#pragma unroll
    for (int i = 0; i < 3; i++) {
        int c = tid + i * 256;
        float y = (vals[i] - mean) * rstd * w[c] + b[c];
        bsplit(y, oh[(size_t)row * DD + c], ol[(size_t)row * DD + c]);
    }
}

// ---------------- effective weight -> hi/lo ----------------
__global__ __launch_bounds__(256) void weff_kernel(const float* __restrict__ Uq, const float* __restrict__ Vq,
                                                   const float* __restrict__ Uk, const float* __restrict__ Vk,
                                                   const float* __restrict__ Uv, const float* __restrict__ Vv,
                                                   bf16* __restrict__ wh, bf16* __restrict__ wl) {
    int idx = blockIdx.x * 256 + threadIdx.x;
    if (idx >= 3 * DD * DD) return;
    int which = idx / (DD * DD);
    int rem = idx % (DD * DD);
    int d = rem / DD, j = rem % DD;
    int hh = j >> 6, e = j & 63;
    const float* U = (which == 0) ? Uq : (which == 1) ? Uk : Uv;
    const float* V = (which == 0) ? Vq : (which == 1) ? Vk : Vv;
    const float* Uhd = U + ((size_t)hh * DD + d) * RA;
    const float* Vh  = V + (size_t)hh * RA * HDD + e;
    float acc = 0.f;
#pragma unroll
    for (int r = 0; r < RA; r++) acc += Uhd[r] * Vh[r * HDD];
    bsplit(acc, wh[idx], wl[idx]);
}

// ---------------- plain split / transpose-split ----------------
__global__ __launch_bounds__(256) void split_kernel(const float* __restrict__ in,
                                                    bf16* __restrict__ oh, bf16* __restrict__ ol, int n) {
    int i = blockIdx.x * 256 + threadIdx.x;
    if (i < n) bsplit(in[i], oh[i], ol[i]);
}
__global__ __launch_bounds__(256) void wo_t_split(const float* __restrict__ Wo,
                                                  bf16* __restrict__ oh, bf16* __restrict__ ol) {
    int idx = blockIdx.x * 256 + threadIdx.x;
    if (idx >= DD * DD) return;
    int k = idx / DD, n = idx % DD;     // out[k][n] = Wo[n][k]
    bsplit(Wo[(size_t)n * DD + k], oh[idx], ol[idx]);
}

// ---------------- bf16x3 split tensor-core GEMM ----------------
// C = (Ah+Al)@(Bh+Bl) approx Ah*Bh + Ah*Bl + Al*Bh, fp32 accum.
// OUTMODE: 0 = fp32 (+bias,+res), 1 = fp32 scatter [B,H,S,HD] (+bias), 2 = split hi/lo (+bias)
template<int OUTMODE>
__global__ __launch_bounds__(512, 1) void gemm_bf3(
    const bf16* __restrict__ Agh, const bf16* __restrict__ Agl,
    const bf16* __restrict__ Bgh, const bf16* __restrict__ Bgl,
    const float* __restrict__ bias, const float* __restrict__ res,
    float* __restrict__ C, bf16* __restrict__ Ch, bf16* __restrict__ Cl,
    int M, int N, int K)
{
    extern __shared__ __align__(16) char smraw[];
    bf16* smb = (bf16*)smraw;
    int tid = threadIdx.x;
    int wid = tid >> 5;
    int warp_m = wid >> 2;   // 0..3
    int warp_n = wid & 3;    // 0..3
    int m0 = blockIdx.y * 128, n0 = blockIdx.x * 128;

    // cp.async mappings
    int arow = tid >> 2;           // 0..127
    int aseg = (tid & 3) * 8;      // bf16 elems
    int brow = tid >> 4;           // 0..31
    int bseg = (tid & 15) * 8;

    const size_t a_goff = (size_t)(m0 + arow) * K + aseg;
    const size_t b_goff = (size_t)brow * N + n0 + bseg;

    auto issue = [&](int c, int st) {
        int k0 = c * BK;
        bf16* sAh = smb + st * STAGE;
        bf16* sAl = sAh + A_TILE;
        bf16* sBh = sAl + A_TILE;
        bf16* sBl = sBh + B_TILE;
        __pipeline_memcpy_async(&sAh[arow * LDAs + aseg], &Agh[a_goff + k0], 16);
        __pipeline_memcpy_async(&sAl[arow * LDAs + aseg], &Agl[a_goff + k0], 16);
        __pipeline_memcpy_async(&sBh[brow * LDBs + bseg], &Bgh[b_goff + (size_t)k0 * N], 16);
        __pipeline_memcpy_async(&sBl[brow * LDBs + bseg], &Bgl[b_goff + (size_t)k0 * N], 16);
    };

    wmma::fragment<wmma::accumulator, 16, 16, 16, float> cf[2][2];
#pragma unroll
    for (int i = 0; i < 2; i++)
#pragma unroll
        for (int j = 0; j < 2; j++) wmma::fill_fragment(cf[i][j], 0.0f);

    int nch = K / BK;
    issue(0, 0); __pipeline_commit();
    if (nch > 1) issue(1, 1);
    __pipeline_commit();

    for (int c = 0; c < nch; c++) {
        __pipeline_wait_prior(1);
        __syncthreads();
        int st = c & 1;
        bf16* sAh = smb + st * STAGE;
        bf16* sAl = sAh + A_TILE;
        bf16* sBh = sAl + A_TILE;
        bf16* sBl = sBh + B_TILE;
#pragma unroll
        for (int ks = 0; ks < 2; ks++) {
            wmma::fragment<wmma::matrix_a, 16, 16, 16, bf16, wmma::row_major> ah[2], al[2];
            wmma::fragment<wmma::matrix_b, 16, 16, 16, bf16, wmma::row_major> bh[2], bl[2];
#pragma unroll
            for (int i = 0; i < 2; i++) {
                wmma::load_matrix_sync(ah[i], &sAh[(warp_m * 32 + i * 16) * LDAs + ks * 16], LDAs);
                wmma::load_matrix_sync(al[i], &sAl[(warp_m * 32 + i * 16) * LDAs + ks * 16], LDAs);
            }
#pragma unroll
            for (int j = 0; j < 2; j++) {
                wmma::load_matrix_sync(bh[j], &sBh[(ks * 16) * LDBs + warp_n * 32 + j * 16], LDBs);
                wmma::load_matrix_sync(bl[j], &sBl[(ks * 16) * LDBs + warp_n * 32 + j * 16], LDBs);
            }
#pragma unroll
            for (int i = 0; i < 2; i++)
#pragma unroll
                for (int j = 0; j < 2; j++) {
                    wmma::mma_sync(cf[i][j], ah[i], bh[j], cf[i][j]);
                    wmma::mma_sync(cf[i][j], ah[i], bl[j], cf[i][j]);
                    wmma::mma_sync(cf[i][j], al[i], bh[j], cf[i][j]);
                }
        }
        __syncthreads();
        if (c + 2 < nch) issue(c + 2, st);
        __pipeline_commit();
    }

    // ---- epilogue: frags -> smem (fp32) -> global ----
    float* Csm = (float*)smraw;
#pragma unroll
    for (int i = 0; i < 2; i++)
#pragma unroll
        for (int j = 0; j < 2; j++)
            wmma::store_matrix_sync(&Csm[(warp_m * 32 + i * 16) * LDC + warp_n * 32 + j * 16],
                                    cf[i][j], LDC, wmma::mem_row_major);
    __syncthreads();

#pragma unroll
    for (int it = 0; it < 8; it++) {
        int idx = tid + it * 512;        // 4096 float4
        int r = idx >> 5;                // 0..127
        int c4 = (idx & 31) << 2;        // 0..124
        float4 v = *(const float4*)&Csm[r * LDC + c4];
        int m = m0 + r, n = n0 + c4;
        if (bias) {
            float4 bb = *(const float4*)&bias[n];
            v.x += bb.x; v.y += bb.y; v.z += bb.z; v.w += bb.w;
        }
        if (res) {
            float4 rr = *(const float4*)&res[(size_t)m * N + n];
            v.x += rr.x; v.y += rr.y; v.z += rr.z; v.w += rr.w;
        }
        if (OUTMODE == 1) {
            int b = m >> 11, s = m & 2047, head = n >> 6, e = n & 63;
            *(float4*)&C[(((size_t)b * HH + head) * SS + s) * HDD + e] = v;
        } else if (OUTMODE == 0) {
            *(float4*)&C[(size_t)m * N + n] = v;
        } else {
            bf16 hv[4], lv[4];
            bsplit(v.x, hv[0], lv[0]); bsplit(v.y, hv[1], lv[1]);
            bsplit(v.z, hv[2], lv[2]); bsplit(v.w, hv[3], lv[3]);
            *(uint2*)&Ch[(size_t)m * N + n] = *(uint2*)hv;
            *(uint2*)&Cl[(size_t)m * N + n] = *(uint2*)lv;
        }
    }
}

// ---------------- RoPE (in place on q and k, layout [B,H,S,HD]) ----------------
__global__ __launch_bounds__(256) void rope_kernel(float* __restrict__ q, float* __restrict__ k,
                                                   const float* __restrict__ cosT,
                                                   const float* __restrict__ sinT) {
    int idx = blockIdx.x * 256 + threadIdx.x;   // B*H*S*32
    if (idx >= BB * HH * SS * 32) return;
    int e = idx & 31;
    int s = (idx >> 5) & 2047;
    int bh = idx >> 16;
    size_t base = ((size_t)bh * SS + s) * HDD;
    float c1 = cosT[s * HDD + e],      s1 = sinT[s * HDD + e];
    float c2 = cosT[s * HDD + e + 32], s2 = sinT[s * HDD + e + 32];
    float q1 = q[base + e], q2 = q[base + e + 32];
    q[base + e]      = q1 * c1 - q2 * s1;
    q[base + e + 32] = q2 * c2 + q1 * s2;
    float k1 = k[base + e], k2 = k[base + e + 32];
    k[base + e]      = k1 * c1 - k2 * s1;
    k[base + e + 32] = k2 * c2 + k1 * s2;
}

// ---------------- flash attention fp32, 128q x 64kc tiles, output hi/lo ----------------
#define P_STRIDE 65
#define ATTN_SMEM_FLOATS (64*128 + 64*64 + 64*64 + 128*P_STRIDE)
__global__ __launch_bounds__(256, 2) void attn2(const float* __restrict__ Q,
                                                const float* __restrict__ K,
                                                const float* __restrict__ V,
                                                bf16* __restrict__ Oh,
                                                bf16* __restrict__ Ol) {
    extern __shared__ float smf[];
    float* Qt = smf;                      // [d][q] stride 128
    float* Kt = smf + 64 * 128;           // [d][kc] stride 64
    float* Vs = Kt + 64 * 64;             // [kc][d] stride 64
    float* Ps = Vs + 64 * 64;             // [q][kc] stride 65

    int tid = threadIdx.x;
    int tx = tid & 15, ty = tid >> 4;
    int bh = blockIdx.y;
    int q0 = blockIdx.x * 128;
    size_t bhoff = (size_t)bh * SS * HDD;

#pragma unroll
    for (int i = 0; i < 8; i++) {
        int idx = tid + i * 256;
        int r = idx >> 4, c4 = (idx & 15) << 2;
        float4 t = *(const float4*)&Q[bhoff + (size_t)(q0 + r) * HDD + c4];
        Qt[(c4 + 0) * 128 + r] = t.x;
        Qt[(c4 + 1) * 128 + r] = t.y;
        Qt[(c4 + 2) * 128 + r] = t.z;
        Qt[(c4 + 3) * 128 + r] = t.w;
    }

    float m_i[8], l_i[8], acc[8][4];
#pragma unroll
    for (int i = 0; i < 8; i++) {
        m_i[i] = -1e30f; l_i[i] = 0.f;
#pragma unroll
        for (int j = 0; j < 4; j++) acc[i][j] = 0.f;
    }
    const float scale = 0.125f;

    for (int kc0 = 0; kc0 < SS; kc0 += 64) {
        __syncthreads();
#pragma unroll
        for (int i = 0; i < 4; i++) {
            int idx = tid + i * 256;
            int r = idx >> 4, c4 = (idx & 15) << 2;
            float4 t = *(const float4*)&K[bhoff + (size_t)(kc0 + r) * HDD + c4];
            Kt[(c4 + 0) * 64 + r] = t.x;
            Kt[(c4 + 1) * 64 + r] = t.y;
            Kt[(c4 + 2) * 64 + r] = t.z;
            Kt[(c4 + 3) * 64 + r] = t.w;
            float4 tv = *(const float4*)&V[bhoff + (size_t)(kc0 + r) * HDD + c4];
            *(float4*)&Vs[r * 64 + c4] = tv;
        }
        __syncthreads();

        float sc[8][4];
#pragma unroll
        for (int i = 0; i < 8; i++)
#pragma unroll
            for (int j = 0; j < 4; j++) sc[i][j] = 0.f;
#pragma unroll
        for (int d = 0; d < 64; d++) {
            float4 a0 = *(const float4*)&Qt[d * 128 + ty * 4];
            float4 a1 = *(const float4*)&Qt[d * 128 + 64 + ty * 4];
            float4 b  = *(const float4*)&Kt[d * 64 + tx * 4];
            float av[8] = {a0.x, a0.y, a0.z, a0.w, a1.x, a1.y, a1.z, a1.w};
            float bv[4] = {b.x, b.y, b.z, b.w};
#pragma unroll
            for (int i = 0; i < 8; i++)
#pragma unroll
                for (int j = 0; j < 4; j++) sc[i][j] += av[i] * bv[j];
        }

        float corr[8];
#pragma unroll
        for (int i = 0; i < 8; i++) {
#pragma unroll
            for (int j = 0; j < 4; j++) sc[i][j] *= scale;
            float rm = fmaxf(fmaxf(sc[i][0], sc[i][1]), fmaxf(sc[i][2], sc[i][3]));
#pragma unroll
            for (int off = 1; off < 16; off <<= 1)
                rm = fmaxf(rm, __shfl_xor_sync(0xffffffffu, rm, off));
            float mn = fmaxf(m_i[i], rm);
            corr[i] = __expf(m_i[i] - mn);
            m_i[i] = mn;
            float rs = 0.f;
#pragma unroll
            for (int j = 0; j < 4; j++) { float pp = __expf(sc[i][j] - mn); sc[i][j] = pp; rs += pp; }
#pragma unroll
            for (int off = 1; off < 16; off <<= 1)
                rs += __shfl_xor_sync(0xffffffffu, rs, off);
            l_i[i] = l_i[i] * corr[i] + rs;
        }

#pragma unroll
        for (int i = 0; i < 8; i++) {
            int qrow = (i < 4) ? (ty * 4 + i) : (64 + ty * 4 + i - 4);
#pragma unroll
            for (int j = 0; j < 4; j++) Ps[qrow * P_STRIDE + tx * 4 + j] = sc[i][j];
        }
        __syncthreads();

#pragma unroll
        for (int i = 0; i < 8; i++)
#pragma unroll
            for (int j = 0; j < 4; j++) acc[i][j] *= corr[i];
#pragma unroll
        for (int kc = 0; kc < 64; kc++) {
            float4 vb = *(const float4*)&Vs[kc * 64 + tx * 4];
            float vv[4] = {vb.x, vb.y, vb.z, vb.w};
            float pv[8];
#pragma unroll
            for (int i = 0; i < 8; i++) {
                int qrow = (i < 4) ? (ty * 4 + i) : (64 + ty * 4 + i - 4);
                pv[i] = Ps[qrow * P_STRIDE + kc];
            }
#pragma unroll
            for (int i = 0; i < 8; i++)
#pragma unroll
                for (int j = 0; j < 4; j++) acc[i][j] += pv[i] * vv[j];
        }
    }

    int b = bh / HH, hd = bh % HH;
#pragma unroll
    for (int i = 0; i < 8; i++) {
        float inv = 1.0f / l_i[i];
        int qrow = q0 + ((i < 4) ? (ty * 4 + i) : (64 + ty * 4 + i - 4));
        size_t base = ((size_t)(b * SS + qrow)) * DD + hd * HDD + tx * 4;
        bf16 hv[4], lv[4];
#pragma unroll
        for (int j = 0; j < 4; j++) bsplit(acc[i][j] * inv, hv[j], lv[j]);
        *(uint2*)&Oh[base] = *(uint2*)hv;
        *(uint2*)&Ol[base] = *(uint2*)lv;
    }
}

// ---------------- GEGLU -> hi/lo ----------------
__global__ __launch_bounds__(256) void geglu_kernel(const float* __restrict__ u,
                                                    bf16* __restrict__ gh, bf16* __restrict__ gl) {
    int idx = blockIdx.x * 256 + threadIdx.x;
    if (idx >= ROWS * DFF) return;
    int row = idx / DFF, col = idx % DFF;
    float x1 = u[(size_t)row * (2 * DFF) + col];
    float x2 = u[(size_t)row * (2 * DFF) + DFF + col];
    float t = 0.7978845608028654f * (x1 + 0.044715f * x1 * x1 * x1);
    float ge = 0.5f * x1 * (1.0f + tanhf(t));
    bsplit(ge * x2, gh[idx], gl[idx]);
}

// ---------------- launch ----------------
extern "C" void kernel_launch(void* const* d_in, const int* in_sizes, int n_in,
                              void* d_out, int out_size) {
    const float* x    = (const float*)d_in[0];
    const float* anw  = (const float*)d_in[1];
    const float* anb  = (const float*)d_in[2];
    const float* Uq   = (const float*)d_in[3];
    const float* Vq   = (const float*)d_in[4];
    const float* bq   = (const float*)d_in[5];
    const float* Uk   = (const float*)d_in[6];
    const float* Vk   = (const float*)d_in[7];
    const float* bk   = (const float*)d_in[8];
    const float* Uv   = (const float*)d_in[9];
    const float* Vv   = (const float*)d_in[10];
    const float* bv   = (const float*)d_in[11];
    const float* Wo_w = (const float*)d_in[12];
    const float* Wo_b = (const float*)d_in[13];
    const float* mnw  = (const float*)d_in[14];
    const float* mnb  = (const float*)d_in[15];
    const float* Ui   = (const float*)d_in[16];
    const float* Vi   = (const float*)d_in[17];
    const float* bi   = (const float*)d_in[18];
    const float* Uo   = (const float*)d_in[19];
    const float* Vo   = (const float*)d_in[20];
    const float* bo   = (const float*)d_in[21];
    const float* cosT = (const float*)d_in[22];
    const float* sinT = (const float*)d_in[23];
    float* out = (float*)d_out;

    bf16 *hh,*hl,*weffh,*weffl,*woth,*wotl,*uih,*uil,*vih,*vil,*uoh,*uol,*voh,*vol;
    bf16 *oh,*ol,*h2h,*h2l,*t1h,*t1l,*gh,*gl,*t2h,*t2l;
    float *q,*k,*v,*x1,*u;
    cudaGetSymbolAddress((void**)&hh, g_hh);   cudaGetSymbolAddress((void**)&hl, g_hl);
    cudaGetSymbolAddress((void**)&weffh, g_weffh); cudaGetSymbolAddress((void**)&weffl, g_weffl);
    cudaGetSymbolAddress((void**)&woth, g_woth);   cudaGetSymbolAddress((void**)&wotl, g_wotl);
    cudaGetSymbolAddress((void**)&uih, g_uih); cudaGetSymbolAddress((void**)&uil, g_uil);
    cudaGetSymbolAddress((void**)&vih, g_vih); cudaGetSymbolAddress((void**)&vil, g_vil);
    cudaGetSymbolAddress((void**)&uoh, g_uoh); cudaGetSymbolAddress((void**)&uol, g_uol);
    cudaGetSymbolAddress((void**)&voh, g_voh); cudaGetSymbolAddress((void**)&vol, g_vol);
    cudaGetSymbolAddress((void**)&q, g_q); cudaGetSymbolAddress((void**)&k, g_k);
    cudaGetSymbolAddress((void**)&v, g_v);
    cudaGetSymbolAddress((void**)&oh, g_oh); cudaGetSymbolAddress((void**)&ol, g_ol);
    cudaGetSymbolAddress((void**)&x1, g_x1);
    cudaGetSymbolAddress((void**)&h2h, g_h2h); cudaGetSymbolAddress((void**)&h2l, g_h2l);
    cudaGetSymbolAddress((void**)&t1h, g_t1h); cudaGetSymbolAddress((void**)&t1l, g_t1l);
    cudaGetSymbolAddress((void**)&u, g_u);
    cudaGetSymbolAddress((void**)&gh, g_gh); cudaGetSymbolAddress((void**)&gl, g_gl);
    cudaGetSymbolAddress((void**)&t2h, g_t2h); cudaGetSymbolAddress((void**)&t2l, g_t2l);

    const int attn_smem = ATTN_SMEM_FLOATS * 4;  // 98816 bytes
    cudaFuncSetAttribute(attn2, cudaFuncAttributeMaxDynamicSharedMemorySize, attn_smem);
    cudaFuncSetAttribute(gemm_bf3<0>, cudaFuncAttributeMaxDynamicSharedMemorySize, GEMM_SMEM);
    cudaFuncSetAttribute(gemm_bf3<1>, cudaFuncAttributeMaxDynamicSharedMemorySize, GEMM_SMEM);
    cudaFuncSetAttribute(gemm_bf3<2>, cudaFuncAttributeMaxDynamicSharedMemorySize, GEMM_SMEM);

    // 1. LN1 -> h hi/lo
    ln_split<<<ROWS, 256>>>(x, anw, anb, hh, hl);
    // 2. weights -> hi/lo planes
    weff_kernel<<<(3 * DD * DD + 255) / 256, 256>>>(Uq, Vq, Uk, Vk, Uv, Vv, weffh, weffl);
    wo_t_split<<<(DD * DD + 255) / 256, 256>>>(Wo_w, woth, wotl);
    split_kernel<<<(DD * RF + 255) / 256, 256>>>(Ui, uih, uil, DD * RF);
    split_kernel<<<(RF * 2 * DFF + 255) / 256, 256>>>(Vi, vih, vil, RF * 2 * DFF);
    split_kernel<<<(DFF * RF + 255) / 256, 256>>>(Uo, uoh, uol, DFF * RF);
    split_kernel<<<(RF * DD + 255) / 256, 256>>>(Vo, voh, vol, RF * DD);
    // 3. Q/K/V projections (scatter into [B,H,S,HD])
    dim3 gQKV(DD / 128, ROWS / 128);
    gemm_bf3<1><<<gQKV, 512, GEMM_SMEM>>>(hh, hl, weffh,             weffl,             bq, nullptr, q, nullptr, nullptr, ROWS, DD, DD);
    gemm_bf3<1><<<gQKV, 512, GEMM_SMEM>>>(hh, hl, weffh + DD * DD,   weffl + DD * DD,   bk, nullptr, k, nullptr, nullptr, ROWS, DD, DD);
    gemm_bf3<1><<<gQKV, 512, GEMM_SMEM>>>(hh, hl, weffh + 2*DD*DD,   weffl + 2*DD*DD,   bv, nullptr, v, nullptr, nullptr, ROWS, DD, DD);
    // 4. RoPE
    rope_kernel<<<(BB * HH * SS * 32 + 255) / 256, 256>>>(q, k, cosT, sinT);
    // 5. attention -> o hi/lo
    attn2<<<dim3(SS / 128, BB * HH), 256, attn_smem>>>(q, k, v, oh, ol);
    // 6. x1 = x + o @ Wo^T + Wo_b
    gemm_bf3<0><<<dim3(DD / 128, ROWS / 128), 512, GEMM_SMEM>>>(oh, ol, woth, wotl, Wo_b, x, x1, nullptr, nullptr, ROWS, DD, DD);
    // 7. LN2 -> h2 hi/lo
    ln_split<<<ROWS, 256>>>(x1, mnw, mnb, h2h, h2l);
    // 8. t1 = h2 @ Ui (split out)
    gemm_bf3<2><<<dim3(RF / 128, ROWS / 128), 512, GEMM_SMEM>>>(h2h, h2l, uih, uil, nullptr, nullptr, nullptr, t1h, t1l, ROWS, RF, DD);
    // 9. u = t1 @ Vi + bi (fp32 out)
    gemm_bf3<0><<<dim3(2 * DFF / 128, ROWS / 128), 512, GEMM_SMEM>>>(t1h, t1l, vih, vil, bi, nullptr, u, nullptr, nullptr, ROWS, 2 * DFF, RF);
    // 10. GEGLU -> g hi/lo
    geglu_kernel<<<(ROWS * DFF + 255) / 256, 256>>>(u, gh, gl);
    // 11. t2 = g @ Uo (split out)
    gemm_bf3<2><<<dim3(RF / 128, ROWS / 128), 512, GEMM_SMEM>>>(gh, gl, uoh, uol, nullptr, nullptr, nullptr, t2h, t2l, ROWS, RF, DFF);
    // 12. out = x1 + t2 @ Vo + bo
    gemm_bf3<0><<<dim3(DD / 128, ROWS / 128), 512, GEMM_SMEM>>>(t2h, t2l, voh, vol, bo, x1, out, nullptr, nullptr, ROWS, DD, RF);
}

// round 5
// speedup vs baseline: 2.2597x; 1.1215x over previous
#include <cuda_runtime.h>
#include <cuda_bf16.h>
#include <cuda_pipeline.h>
#include <mma.h>
#include <math.h>

using namespace nvcuda;

// ---------------- problem constants ----------------
#define BB 4
#define SS 2048
#define DD 768
#define HH 12
#define HDD 64
#define RA 32
#define RF 512
#define DFF 3072
#define ROWS (BB*SS)          // 8192

// ---------------- GEMM tile constants ----------------
#define BK 32
#define LDAs 48
#define LDBs 136
#define A_TILE (128*LDAs)
#define B_TILE (BK*LDBs)
#define STAGE (2*A_TILE + 2*B_TILE)
#define GEMM_SMEM (2*STAGE*2)
#define LDC 132

typedef __nv_bfloat16 bf16;

// ---------------- scratch ----------------
__device__ bf16  g_hh [ROWS*DD];
__device__ bf16  g_hl [ROWS*DD];
__device__ bf16  g_weffh[3*DD*DD];
__device__ bf16  g_weffl[3*DD*DD];
__device__ bf16  g_woth[DD*DD];
__device__ bf16  g_wotl[DD*DD];
__device__ bf16  g_uih[DD*RF],  g_uil[DD*RF];
__device__ bf16  g_vih[RF*2*DFF], g_vil[RF*2*DFF];
__device__ bf16  g_uoh[DFF*RF], g_uol[DFF*RF];
__device__ bf16  g_voh[RF*DD],  g_vol[RF*DD];
__device__ float g_q  [ROWS*DD];      // [B,H,S,HD] fp32 (pre-rope)
__device__ float g_k  [ROWS*DD];
__device__ bf16  g_qh [ROWS*DD], g_ql[ROWS*DD];   // post-rope, q scaled by 0.125
__device__ bf16  g_kh [ROWS*DD], g_kl[ROWS*DD];
__device__ bf16  g_vh [ROWS*DD], g_vl[ROWS*DD];
__device__ bf16  g_oh [ROWS*DD];      // [B,S,D]
__device__ bf16  g_ol [ROWS*DD];
__device__ float g_x1 [ROWS*DD];
__device__ bf16  g_h2h[ROWS*DD];
__device__ bf16  g_h2l[ROWS*DD];
__device__ bf16  g_t1h[ROWS*RF], g_t1l[ROWS*RF];
__device__ float g_u  [ROWS*2*DFF];
__device__ bf16  g_gh [ROWS*DFF], g_gl[ROWS*DFF];
__device__ bf16  g_t2h[ROWS*RF], g_t2l[ROWS*RF];

__device__ __forceinline__ void bsplit(float a, bf16& h, bf16& l) {
    h = __float2bfloat16(a);
    l = __float2bfloat16(a - __bfloat162float(h));
}
__device__ __forceinline__ unsigned pack2(bf16 a, bf16 b) {
    __nv_bfloat162 t(a, b);
    return *(unsigned*)&t;
}

// ---------------- layernorm -> bf16 hi/lo ----------------
__global__ __launch_bounds__(256) void ln_split(const float* __restrict__ x,
                                                const float* __restrict__ w,
                                                const float* __restrict__ b,
                                                bf16* __restrict__ oh,
                                                bf16* __restrict__ ol) {
    int row = blockIdx.x;
    const float* xr = x + (size_t)row * DD;
    float vals[3];
    float s = 0.f, s2 = 0.f;
    int tid = threadIdx.x;
#pragma unroll
    for (int i = 0; i < 3; i++) {
        float v = xr[tid + i * 256];
        vals[i] = v; s += v; s2 += v * v;
    }
    __shared__ float sh[256], sh2[256];
    sh[tid] = s; sh2[tid] = s2;
    __syncthreads();
    for (int off = 128; off > 0; off >>= 1) {
        if (tid < off) { sh[tid] += sh[tid + off]; sh2[tid] += sh2[tid + off]; }
        __syncthreads();
    }
    float mean = sh[0] * (1.0f / DD);
    float var  = sh2[0] * (1.0f / DD) - mean * mean;
    float rstd = rsqrtf(var + 1e-6f);
#pragma unroll
    for (int i = 0; i < 3; i++) {
        int c = tid + i * 256;
        float y = (vals[i] - mean) * rstd * w[c] + b[c];
        bsplit(y, oh[(size_t)row * DD + c], ol[(size_t)row * DD + c]);
    }
}

// ---------------- effective weight -> hi/lo ----------------
__global__ __launch_bounds__(256) void weff_kernel(const float* __restrict__ Uq, const float* __restrict__ Vq,
                                                   const float* __restrict__ Uk, const float* __restrict__ Vk,
                                                   const float* __restrict__ Uv, const float* __restrict__ Vv,
                                                   bf16* __restrict__ wh, bf16* __restrict__ wl) {
    int idx = blockIdx.x * 256 + threadIdx.x;
    if (idx >= 3 * DD * DD) return;
    int which = idx / (DD * DD);
    int rem = idx % (DD * DD);
    int d = rem / DD, j = rem % DD;
    int hh = j >> 6, e = j & 63;
    const float* U = (which == 0) ? Uq : (which == 1) ? Uk : Uv;
    const float* V = (which == 0) ? Vq : (which == 1) ? Vk : Vv;
    const float* Uhd = U + ((size_t)hh * DD + d) * RA;
    const float* Vh  = V + (size_t)hh * RA * HDD + e;
    float acc = 0.f;
#pragma unroll
    for (int r = 0; r < RA; r++) acc += Uhd[r] * Vh[r * HDD];
    bsplit(acc, wh[idx], wl[idx]);
}

// ---------------- plain split / transpose-split ----------------
__global__ __launch_bounds__(256) void split_kernel(const float* __restrict__ in,
                                                    bf16* __restrict__ oh, bf16* __restrict__ ol, int n) {
    int i = blockIdx.x * 256 + threadIdx.x;
    if (i < n) bsplit(in[i], oh[i], ol[i]);
}
__global__ __launch_bounds__(256) void wo_t_split(const float* __restrict__ Wo,
                                                  bf16* __restrict__ oh, bf16* __restrict__ ol) {
    int idx = blockIdx.x * 256 + threadIdx.x;
    if (idx >= DD * DD) return;
    int k = idx / DD, n = idx % DD;
    bsplit(Wo[(size_t)n * DD + k], oh[idx], ol[idx]);
}

// ---------------- bf16x3 split tensor-core GEMM ----------------
// OUTMODE: 0 fp32 (+bias,+res); 1 fp32 scatter (+bias); 2 split hi/lo; 3 scatter split (+bias)
template<int OUTMODE>
__global__ __launch_bounds__(512, 1) void gemm_bf3(
    const bf16* __restrict__ Agh, const bf16* __restrict__ Agl,
    const bf16* __restrict__ Bgh, const bf16* __restrict__ Bgl,
    const float* __restrict__ bias, const float* __restrict__ res,
    float* __restrict__ C, bf16* __restrict__ Ch, bf16* __restrict__ Cl,
    int M, int N, int K)
{
    extern __shared__ __align__(16) char smraw[];
    bf16* smb = (bf16*)smraw;
    int tid = threadIdx.x;
    int wid = tid >> 5;
    int warp_m = wid >> 2;
    int warp_n = wid & 3;
    int m0 = blockIdx.y * 128, n0 = blockIdx.x * 128;

    int arow = tid >> 2;
    int aseg = (tid & 3) * 8;
    int brow = tid >> 4;
    int bseg = (tid & 15) * 8;

    const size_t a_goff = (size_t)(m0 + arow) * K + aseg;
    const size_t b_goff = (size_t)brow * N + n0 + bseg;

    auto issue = [&](int c, int st) {
        int k0 = c * BK;
        bf16* sAh = smb + st * STAGE;
        bf16* sAl = sAh + A_TILE;
        bf16* sBh = sAl + A_TILE;
        bf16* sBl = sBh + B_TILE;
        __pipeline_memcpy_async(&sAh[arow * LDAs + aseg], &Agh[a_goff + k0], 16);
        __pipeline_memcpy_async(&sAl[arow * LDAs + aseg], &Agl[a_goff + k0], 16);
        __pipeline_memcpy_async(&sBh[brow * LDBs + bseg], &Bgh[b_goff + (size_t)k0 * N], 16);
        __pipeline_memcpy_async(&sBl[brow * LDBs + bseg], &Bgl[b_goff + (size_t)k0 * N], 16);
    };

    wmma::fragment<wmma::accumulator, 16, 16, 16, float> cf[2][2];
#pragma unroll
    for (int i = 0; i < 2; i++)
#pragma unroll
        for (int j = 0; j < 2; j++) wmma::fill_fragment(cf[i][j], 0.0f);

    int nch = K / BK;
    issue(0, 0); __pipeline_commit();
    if (nch > 1) issue(1, 1);
    __pipeline_commit();

    for (int c = 0; c < nch; c++) {
        __pipeline_wait_prior(1);
        __syncthreads();
        int st = c & 1;
        bf16* sAh = smb + st * STAGE;
        bf16* sAl = sAh + A_TILE;
        bf16* sBh = sAl + A_TILE;
        bf16* sBl = sBh + B_TILE;
#pragma unroll
        for (int ks = 0; ks < 2; ks++) {
            wmma::fragment<wmma::matrix_a, 16, 16, 16, bf16, wmma::row_major> ah[2], al[2];
            wmma::fragment<wmma::matrix_b, 16, 16, 16, bf16, wmma::row_major> bh[2], bl[2];
#pragma unroll
            for (int i = 0; i < 2; i++) {
                wmma::load_matrix_sync(ah[i], &sAh[(warp_m * 32 + i * 16) * LDAs + ks * 16], LDAs);
                wmma::load_matrix_sync(al[i], &sAl[(warp_m * 32 + i * 16) * LDAs + ks * 16], LDAs);
            }
#pragma unroll
            for (int j = 0; j < 2; j++) {
                wmma::load_matrix_sync(bh[j], &sBh[(ks * 16) * LDBs + warp_n * 32 + j * 16], LDBs);
                wmma::load_matrix_sync(bl[j], &sBl[(ks * 16) * LDBs + warp_n * 32 + j * 16], LDBs);
            }
#pragma unroll
            for (int i = 0; i < 2; i++)
#pragma unroll
                for (int j = 0; j < 2; j++) {
                    wmma::mma_sync(cf[i][j], ah[i], bh[j], cf[i][j]);
                    wmma::mma_sync(cf[i][j], ah[i], bl[j], cf[i][j]);
                    wmma::mma_sync(cf[i][j], al[i], bh[j], cf[i][j]);
                }
        }
        __syncthreads();
        if (c + 2 < nch) issue(c + 2, st);
        __pipeline_commit();
    }

    float* Csm = (float*)smraw;
#pragma unroll
    for (int i = 0; i < 2; i++)
#pragma unroll
        for (int j = 0; j < 2; j++)
            wmma::store_matrix_sync(&Csm[(warp_m * 32 + i * 16) * LDC + warp_n * 32 + j * 16],
                                    cf[i][j], LDC, wmma::mem_row_major);
    __syncthreads();

#pragma unroll
    for (int it = 0; it < 8; it++) {
        int idx = tid + it * 512;
        int r = idx >> 5;
        int c4 = (idx & 31) << 2;
        float4 v = *(const float4*)&Csm[r * LDC + c4];
        int m = m0 + r, n = n0 + c4;
        if (bias) {
            float4 bb = *(const float4*)&bias[n];
            v.x += bb.x; v.y += bb.y; v.z += bb.z; v.w += bb.w;
        }
        if (res) {
            float4 rr = *(const float4*)&res[(size_t)m * N + n];
            v.x += rr.x; v.y += rr.y; v.z += rr.z; v.w += rr.w;
        }
        if (OUTMODE == 1) {
            int b = m >> 11, s = m & 2047, head = n >> 6, e = n & 63;
            *(float4*)&C[(((size_t)b * HH + head) * SS + s) * HDD + e] = v;
        } else if (OUTMODE == 0) {
            *(float4*)&C[(size_t)m * N + n] = v;
        } else if (OUTMODE == 2) {
            bf16 hv[4], lv[4];
            bsplit(v.x, hv[0], lv[0]); bsplit(v.y, hv[1], lv[1]);
            bsplit(v.z, hv[2], lv[2]); bsplit(v.w, hv[3], lv[3]);
            *(uint2*)&Ch[(size_t)m * N + n] = *(uint2*)hv;
            *(uint2*)&Cl[(size_t)m * N + n] = *(uint2*)lv;
        } else {
            int b = m >> 11, s = m & 2047, head = n >> 6, e = n & 63;
            size_t o = (((size_t)b * HH + head) * SS + s) * HDD + e;
            bf16 hv[4], lv[4];
            bsplit(v.x, hv[0], lv[0]); bsplit(v.y, hv[1], lv[1]);
            bsplit(v.z, hv[2], lv[2]); bsplit(v.w, hv[3], lv[3]);
            *(uint2*)&Ch[o] = *(uint2*)hv;
            *(uint2*)&Cl[o] = *(uint2*)lv;
        }
    }
}

// ---------------- RoPE + split (q scaled by 0.125) ----------------
__global__ __launch_bounds__(256) void rope_split(const float* __restrict__ q, const float* __restrict__ k,
                                                  const float* __restrict__ cosT, const float* __restrict__ sinT,
                                                  bf16* __restrict__ qh, bf16* __restrict__ ql,
                                                  bf16* __restrict__ kh, bf16* __restrict__ kl) {
    int idx = blockIdx.x * 256 + threadIdx.x;
    if (idx >= BB * HH * SS * 32) return;
    int e = idx & 31;
    int s = (idx >> 5) & 2047;
    int bh = idx >> 16;
    size_t base = ((size_t)bh * SS + s) * HDD;
    float c1 = cosT[s * HDD + e],      s1 = sinT[s * HDD + e];
    float c2 = cosT[s * HDD + e + 32], s2 = sinT[s * HDD + e + 32];
    float q1 = q[base + e], q2 = q[base + e + 32];
    float qa = (q1 * c1 - q2 * s1) * 0.125f;
    float qb = (q2 * c2 + q1 * s2) * 0.125f;
    bsplit(qa, qh[base + e],      ql[base + e]);
    bsplit(qb, qh[base + e + 32], ql[base + e + 32]);
    float k1 = k[base + e], k2 = k[base + e + 32];
    float ka = k1 * c1 - k2 * s1;
    float kb = k2 * c2 + k1 * s2;
    bsplit(ka, kh[base + e],      kl[base + e]);
    bsplit(kb, kh[base + e + 32], kl[base + e + 32]);
}

// ---------------- tensor-core flash attention (bf16x3) ----------------
// 128 q x 64 kc tile, 8 warps x 16 q-rows, S/O staged in smem fp32.
#define LDQ 72
#define LDKV 72
#define LDP 72
#define LDSS 68
#define LDO 68
#define ATT_SMEM (( (4*128*LDQ/2 + 4*64*LDKV) /*bf16 elems: Qh Ql Ph Pl + K/V*/ )*0 + 180224)
__global__ __launch_bounds__(256, 1) void attn_tc(
    const bf16* __restrict__ Qh_, const bf16* __restrict__ Ql_,
    const bf16* __restrict__ Kh_, const bf16* __restrict__ Kl_,
    const bf16* __restrict__ Vh_, const bf16* __restrict__ Vl_,
    bf16* __restrict__ Oh_, bf16* __restrict__ Ol_)
{
    extern __shared__ __align__(16) char smraw_[];
    bf16* sQh = (bf16*)smraw_;            // 128*72
    bf16* sQl = sQh + 128 * LDQ;
    bf16* sKh = sQl + 128 * LDQ;          // 64*72
    bf16* sKl = sKh + 64 * LDKV;
    bf16* sVh = sKl + 64 * LDKV;
    bf16* sVl = sVh + 64 * LDKV;
    bf16* sPh = sVl + 64 * LDKV;          // 128*72
    bf16* sPl = sPh + 128 * LDP;
    float* sS = (float*)(sPl + 128 * LDP);   // 128*68
    float* sO = sS + 128 * LDSS;             // 128*68

    int tid = threadIdx.x;
    int warp = tid >> 5;
    int bh = blockIdx.y;
    int q0 = blockIdx.x * 128;
    size_t qoff = ((size_t)bh * SS + q0) * HDD;

    // load Q tiles (hi/lo), 8 bf16 per uint4
#pragma unroll
    for (int i = 0; i < 4; i++) {
        int idx = tid + i * 256;             // 1024 per plane
        int r = idx >> 3, c8 = (idx & 7) * 8;
        *(uint4*)&sQh[r * LDQ + c8] = *(const uint4*)&Qh_[qoff + (size_t)r * HDD + c8];
        *(uint4*)&sQl[r * LDQ + c8] = *(const uint4*)&Ql_[qoff + (size_t)r * HDD + c8];
    }
    // zero O
#pragma unroll
    for (int i = 0; i < 34; i++) sO[tid + i * 256] = 0.f;

    float m = -1e30f, l = 0.f;
    int r = tid >> 1, c0 = (tid & 1) * 32;

    for (int kc0 = 0; kc0 < SS; kc0 += 64) {
        __syncthreads();
        size_t koff = ((size_t)bh * SS + kc0) * HDD;
#pragma unroll
        for (int i = 0; i < 2; i++) {
            int idx = tid + i * 256;         // 512 per plane
            int rr = idx >> 3, c8 = (idx & 7) * 8;
            *(uint4*)&sKh[rr * LDKV + c8] = *(const uint4*)&Kh_[koff + (size_t)rr * HDD + c8];
            *(uint4*)&sKl[rr * LDKV + c8] = *(const uint4*)&Kl_[koff + (size_t)rr * HDD + c8];
            *(uint4*)&sVh[rr * LDKV + c8] = *(const uint4*)&Vh_[koff + (size_t)rr * HDD + c8];
            *(uint4*)&sVl[rr * LDKV + c8] = *(const uint4*)&Vl_[koff + (size_t)rr * HDD + c8];
        }
        __syncthreads();

        // ---- S = Qh*Kh + Qh*Kl + Ql*Kh ----
        {
            wmma::fragment<wmma::accumulator, 16, 16, 16, float> sf[4];
#pragma unroll
            for (int j = 0; j < 4; j++) wmma::fill_fragment(sf[j], 0.f);
#pragma unroll
            for (int ks = 0; ks < 4; ks++) {
                wmma::fragment<wmma::matrix_a, 16, 16, 16, bf16, wmma::row_major> ah, al;
                wmma::load_matrix_sync(ah, &sQh[(warp * 16) * LDQ + ks * 16], LDQ);
                wmma::load_matrix_sync(al, &sQl[(warp * 16) * LDQ + ks * 16], LDQ);
#pragma unroll
                for (int j = 0; j < 4; j++) {
                    wmma::fragment<wmma::matrix_b, 16, 16, 16, bf16, wmma::col_major> bhf, blf;
                    wmma::load_matrix_sync(bhf, &sKh[(j * 16) * LDKV + ks * 16], LDKV);
                    wmma::load_matrix_sync(blf, &sKl[(j * 16) * LDKV + ks * 16], LDKV);
                    wmma::mma_sync(sf[j], ah, bhf, sf[j]);
                    wmma::mma_sync(sf[j], ah, blf, sf[j]);
                    wmma::mma_sync(sf[j], al, bhf, sf[j]);
                }
            }
#pragma unroll
            for (int j = 0; j < 4; j++)
                wmma::store_matrix_sync(&sS[(warp * 16) * LDSS + j * 16], sf[j], LDSS, wmma::mem_row_major);
        }
        __syncthreads();

        // ---- online softmax (thread pair per row) ----
        {
            const float* srow = sS + r * LDSS + c0;
            float tmax = -1e30f;
#pragma unroll
            for (int cc = 0; cc < 8; cc++) {
                float4 sv = *(const float4*)&srow[cc * 4];
                tmax = fmaxf(tmax, fmaxf(fmaxf(sv.x, sv.y), fmaxf(sv.z, sv.w)));
            }
            tmax = fmaxf(tmax, __shfl_xor_sync(0xffffffffu, tmax, 1));
            float mnew = fmaxf(m, tmax);
            float corr = __expf(m - mnew);
            float sum = 0.f;
            unsigned* ph = (unsigned*)&sPh[r * LDP + c0];
            unsigned* pl = (unsigned*)&sPl[r * LDP + c0];
#pragma unroll
            for (int cc = 0; cc < 8; cc++) {
                float4 sv = *(const float4*)&srow[cc * 4];
                float p0 = __expf(sv.x - mnew), p1 = __expf(sv.y - mnew);
                float p2 = __expf(sv.z - mnew), p3 = __expf(sv.w - mnew);
                sum += (p0 + p1) + (p2 + p3);
                bf16 h0, l0, h1, l1, h2, l2, h3, l3;
                bsplit(p0, h0, l0); bsplit(p1, h1, l1);
                bsplit(p2, h2, l2); bsplit(p3, h3, l3);
                uint2 uh = { pack2(h0, h1), pack2(h2, h3) };
                uint2 ul = { pack2(l0, l1), pack2(l2, l3) };
                *(uint2*)&ph[cc * 2] = uh;
                *(uint2*)&pl[cc * 2] = ul;
            }
            sum += __shfl_xor_sync(0xffffffffu, sum, 1);
            l = l * corr + sum;
            m = mnew;
            // rescale O
            float* orow = sO + r * LDO + c0;
#pragma unroll
            for (int cc = 0; cc < 8; cc++) {
                float4 ov = *(const float4*)&orow[cc * 4];
                ov.x *= corr; ov.y *= corr; ov.z *= corr; ov.w *= corr;
                *(float4*)&orow[cc * 4] = ov;
            }
        }
        __syncthreads();

        // ---- O += Ph*Vh + Pl*Vh + Ph*Vl ----
        {
            wmma::fragment<wmma::matrix_a, 16, 16, 16, bf16, wmma::row_major> pah[4], pal[4];
#pragma unroll
            for (int ks = 0; ks < 4; ks++) {
                wmma::load_matrix_sync(pah[ks], &sPh[(warp * 16) * LDP + ks * 16], LDP);
                wmma::load_matrix_sync(pal[ks], &sPl[(warp * 16) * LDP + ks * 16], LDP);
            }
#pragma unroll
            for (int j = 0; j < 4; j++) {
                wmma::fragment<wmma::accumulator, 16, 16, 16, float> of;
                wmma::load_matrix_sync(of, &sO[(warp * 16) * LDO + j * 16], LDO, wmma::mem_row_major);
#pragma unroll
                for (int ks = 0; ks < 4; ks++) {
                    wmma::fragment<wmma::matrix_b, 16, 16, 16, bf16, wmma::row_major> vbh, vbl;
                    wmma::load_matrix_sync(vbh, &sVh[(ks * 16) * LDKV + j * 16], LDKV);
                    wmma::load_matrix_sync(vbl, &sVl[(ks * 16) * LDKV + j * 16], LDKV);
                    wmma::mma_sync(of, pah[ks], vbh, of);
                    wmma::mma_sync(of, pal[ks], vbh, of);
                    wmma::mma_sync(of, pah[ks], vbl, of);
                }
                wmma::store_matrix_sync(&sO[(warp * 16) * LDO + j * 16], of, LDO, wmma::mem_row_major);
            }
        }
    }
    __syncthreads();

    // ---- epilogue: O / l -> hi/lo planes in [B,S,D] ----
    int b = bh / HH, hd = bh % HH;
    float inv = 1.0f / l;
    size_t obase = ((size_t)(b * SS + q0 + r)) * DD + hd * HDD + c0;
    const float* orow = sO + r * LDO + c0;
#pragma unroll
    for (int cc = 0; cc < 8; cc++) {
        float4 ov = *(const float4*)&orow[cc * 4];
        bf16 h0, l0, h1, l1, h2, l2, h3, l3;
        bsplit(ov.x * inv, h0, l0); bsplit(ov.y * inv, h1, l1);
        bsplit(ov.z * inv, h2, l2); bsplit(ov.w * inv, h3, l3);
        uint2 uh = { pack2(h0, h1), pack2(h2, h3) };
        uint2 ul = { pack2(l0, l1), pack2(l2, l3) };
        *(uint2*)&Oh_[obase + cc * 4] = uh;
        *(uint2*)&Ol_[obase + cc * 4] = ul;
    }
}

// ---------------- GEGLU -> hi/lo ----------------
__global__ __launch_bounds__(256) void geglu_kernel(const float* __restrict__ u,
                                                    bf16* __restrict__ gh, bf16* __restrict__ gl) {
    int idx = blockIdx.x * 256 + threadIdx.x;
    if (idx >= ROWS * DFF) return;
    int row = idx / DFF, col = idx % DFF;
    float x1 = u[(size_t)row * (2 * DFF) + col];
    float x2 = u[(size_t)row * (2 * DFF) + DFF + col];
    float t = 0.7978845608028654f * (x1 + 0.044715f * x1 * x1 * x1);
    float ge = 0.5f * x1 * (1.0f + tanhf(t));
    bsplit(ge * x2, gh[idx], gl[idx]);
}

// ---------------- launch ----------------
extern "C" void kernel_launch(void* const* d_in, const int* in_sizes, int n_in,
                              void* d_out, int out_size) {
    const float* x    = (const float*)d_in[0];
    const float* anw  = (const float*)d_in[1];
    const float* anb  = (const float*)d_in[2];
    const float* Uq   = (const float*)d_in[3];
    const float* Vq   = (const float*)d_in[4];
    const float* bq   = (const float*)d_in[5];
    const float* Uk   = (const float*)d_in[6];
    const float* Vk   = (const float*)d_in[7];
    const float* bk   = (const float*)d_in[8];
    const float* Uv   = (const float*)d_in[9];
    const float* Vv   = (const float*)d_in[10];
    const float* bv   = (const float*)d_in[11];
    const float* Wo_w = (const float*)d_in[12];
    const float* Wo_b = (const float*)d_in[13];
    const float* mnw  = (const float*)d_in[14];
    const float* mnb  = (const float*)d_in[15];
    const float* Ui   = (const float*)d_in[16];
    const float* Vi   = (const float*)d_in[17];
    const float* bi   = (const float*)d_in[18];
    const float* Uo   = (const float*)d_in[19];
    const float* Vo   = (const float*)d_in[20];
    const float* bo   = (const float*)d_in[21];
    const float* cosT = (const float*)d_in[22];
    const float* sinT = (const float*)d_in[23];
    float* out = (float*)d_out;

    bf16 *hh,*hl,*weffh,*weffl,*woth,*wotl,*uih,*uil,*vih,*vil,*uoh,*uol,*voh,*vol;
    bf16 *qh,*ql,*kh,*kl,*vh,*vl,*oh,*ol,*h2h,*h2l,*t1h,*t1l,*gh,*gl,*t2h,*t2l;
    float *q,*k,*x1,*u;
    cudaGetSymbolAddress((void**)&hh, g_hh);   cudaGetSymbolAddress((void**)&hl, g_hl);
    cudaGetSymbolAddress((void**)&weffh, g_weffh); cudaGetSymbolAddress((void**)&weffl, g_weffl);
    cudaGetSymbolAddress((void**)&woth, g_woth);   cudaGetSymbolAddress((void**)&wotl, g_wotl);
    cudaGetSymbolAddress((void**)&uih, g_uih); cudaGetSymbolAddress((void**)&uil, g_uil);
    cudaGetSymbolAddress((void**)&vih, g_vih); cudaGetSymbolAddress((void**)&vil, g_vil);
    cudaGetSymbolAddress((void**)&uoh, g_uoh); cudaGetSymbolAddress((void**)&uol, g_uol);
    cudaGetSymbolAddress((void**)&voh, g_voh); cudaGetSymbolAddress((void**)&vol, g_vol);
    cudaGetSymbolAddress((void**)&q, g_q); cudaGetSymbolAddress((void**)&k, g_k);
    cudaGetSymbolAddress((void**)&qh, g_qh); cudaGetSymbolAddress((void**)&ql, g_ql);
    cudaGetSymbolAddress((void**)&kh, g_kh); cudaGetSymbolAddress((void**)&kl, g_kl);
    cudaGetSymbolAddress((void**)&vh, g_vh); cudaGetSymbolAddress((void**)&vl, g_vl);
    cudaGetSymbolAddress((void**)&oh, g_oh); cudaGetSymbolAddress((void**)&ol, g_ol);
    cudaGetSymbolAddress((void**)&x1, g_x1);
    cudaGetSymbolAddress((void**)&h2h, g_h2h); cudaGetSymbolAddress((void**)&h2l, g_h2l);
    cudaGetSymbolAddress((void**)&t1h, g_t1h); cudaGetSymbolAddress((void**)&t1l, g_t1l);
    cudaGetSymbolAddress((void**)&u, g_u);
    cudaGetSymbolAddress((void**)&gh, g_gh); cudaGetSymbolAddress((void**)&gl, g_gl);
    cudaGetSymbolAddress((void**)&t2h, g_t2h); cudaGetSymbolAddress((void**)&t2l, g_t2l);

    const int att_smem = 180224;
    cudaFuncSetAttribute(attn_tc, cudaFuncAttributeMaxDynamicSharedMemorySize, att_smem);
    cudaFuncSetAttribute(gemm_bf3<0>, cudaFuncAttributeMaxDynamicSharedMemorySize, GEMM_SMEM);
    cudaFuncSetAttribute(gemm_bf3<1>, cudaFuncAttributeMaxDynamicSharedMemorySize, GEMM_SMEM);
    cudaFuncSetAttribute(gemm_bf3<2>, cudaFuncAttributeMaxDynamicSharedMemorySize, GEMM_SMEM);
    cudaFuncSetAttribute(gemm_bf3<3>, cudaFuncAttributeMaxDynamicSharedMemorySize, GEMM_SMEM);

    // 1. LN1
    ln_split<<<ROWS, 256>>>(x, anw, anb, hh, hl);
    // 2. weights -> hi/lo
    weff_kernel<<<(3 * DD * DD + 255) / 256, 256>>>(Uq, Vq, Uk, Vk, Uv, Vv, weffh, weffl);
    wo_t_split<<<(DD * DD + 255) / 256, 256>>>(Wo_w, woth, wotl);
    split_kernel<<<(DD * RF + 255) / 256, 256>>>(Ui, uih, uil, DD * RF);
    split_kernel<<<(RF * 2 * DFF + 255) / 256, 256>>>(Vi, vih, vil, RF * 2 * DFF);
    split_kernel<<<(DFF * RF + 255) / 256, 256>>>(Uo, uoh, uol, DFF * RF);
    split_kernel<<<(RF * DD + 255) / 256, 256>>>(Vo, voh, vol, RF * DD);
    // 3. Q/K (fp32 scatter), V (scatter + split)
    dim3 gQKV(DD / 128, ROWS / 128);
    gemm_bf3<1><<<gQKV, 512, GEMM_SMEM>>>(hh, hl, weffh,           weffl,           bq, nullptr, q, nullptr, nullptr, ROWS, DD, DD);
    gemm_bf3<1><<<gQKV, 512, GEMM_SMEM>>>(hh, hl, weffh + DD * DD, weffl + DD * DD, bk, nullptr, k, nullptr, nullptr, ROWS, DD, DD);
    gemm_bf3<3><<<gQKV, 512, GEMM_SMEM>>>(hh, hl, weffh + 2*DD*DD, weffl + 2*DD*DD, bv, nullptr, nullptr, vh, vl, ROWS, DD, DD);
    // 4. RoPE + split
    rope_split<<<(BB * HH * SS * 32 + 255) / 256, 256>>>(q, k, cosT, sinT, qh, ql, kh, kl);
    // 5. tensor-core attention -> o hi/lo
    attn_tc<<<dim3(SS / 128, BB * HH), 256, att_smem>>>(qh, ql, kh, kl, vh, vl, oh, ol);
    // 6. x1 = x + o @ Wo^T + Wo_b
    gemm_bf3<0><<<dim3(DD / 128, ROWS / 128), 512, GEMM_SMEM>>>(oh, ol, woth, wotl, Wo_b, x, x1, nullptr, nullptr, ROWS, DD, DD);
    // 7. LN2
    ln_split<<<ROWS, 256>>>(x1, mnw, mnb, h2h, h2l);
    // 8. t1 = h2 @ Ui
    gemm_bf3<2><<<dim3(RF / 128, ROWS / 128), 512, GEMM_SMEM>>>(h2h, h2l, uih, uil, nullptr, nullptr, nullptr, t1h, t1l, ROWS, RF, DD);
    // 9. u = t1 @ Vi + bi
    gemm_bf3<0><<<dim3(2 * DFF / 128, ROWS / 128), 512, GEMM_SMEM>>>(t1h, t1l, vih, vil, bi, nullptr, u, nullptr, nullptr, ROWS, 2 * DFF, RF);
    // 10. GEGLU
    geglu_kernel<<<(ROWS * DFF + 255) / 256, 256>>>(u, gh, gl);
    // 11. t2 = g @ Uo
    gemm_bf3<2><<<dim3(RF / 128, ROWS / 128), 512, GEMM_SMEM>>>(gh, gl, uoh, uol, nullptr, nullptr, nullptr, t2h, t2l, ROWS, RF, DFF);
    // 12. out = x1 + t2 @ Vo + bo
    gemm_bf3<0><<<dim3(DD / 128, ROWS / 128), 512, GEMM_SMEM>>>(t2h, t2l, voh, vol, bo, x1, out, nullptr, nullptr, ROWS, DD, RF);
}

// round 7
// speedup vs baseline: 2.7064x; 1.1977x over previous
#include <cuda_runtime.h>
#include <cuda_bf16.h>
#include <cuda_pipeline.h>
#include <mma.h>
#include <math.h>
#include <cstdint>

using namespace nvcuda;

// ---------------- problem constants ----------------
#define BB 4
#define SS 2048
#define DD 768
#define HH 12
#define HDD 64
#define RA 32
#define RF 512
#define DFF 3072
#define ROWS (BB*SS)          // 8192

// ---------------- GEMM tile constants ----------------
#define BK 32
#define LDAs 40               // bf16 elems (80B rows, 16B aligned)
#define LDBs 136              // bf16 elems (272B rows)
#define A_TILE (128*LDAs)     // 5120
#define B_TILE (BK*LDBs)      // 4352
#define STAGE (2*A_TILE + 2*B_TILE)   // 18944 bf16
#define GEMM_SMEM (2*STAGE*2)         // 75776 bytes
#define LDC 132               // Csm floats: 128*132*4 = 67584 <= 75776

typedef __nv_bfloat16 bf16;

// ---------------- scratch ----------------
__device__ bf16  g_hh [ROWS*DD];
__device__ bf16  g_hl [ROWS*DD];
__device__ bf16  g_weffh[3*DD*DD];     // [which][k][n]
__device__ bf16  g_weffl[3*DD*DD];
__device__ bf16  g_woth[DD*DD];        // Wo^T [k][n]
__device__ bf16  g_wotl[DD*DD];
__device__ bf16  g_uih[DD*RF],  g_uil[DD*RF];
__device__ bf16  g_vih[RF*2*DFF], g_vil[RF*2*DFF];    // column-interleaved (g1,g2 pairs)
__device__ bf16  g_uoh[DFF*RF], g_uol[DFF*RF];
__device__ bf16  g_voh[RF*DD],  g_vol[RF*DD];
__device__ bf16  g_qh [ROWS*DD], g_ql[ROWS*DD];   // [B,H,S,HD] post-rope, q scaled
__device__ bf16  g_kh [ROWS*DD], g_kl[ROWS*DD];
__device__ bf16  g_vh [ROWS*DD], g_vl[ROWS*DD];
__device__ bf16  g_oh [ROWS*DD], g_ol[ROWS*DD];
__device__ float g_x1 [ROWS*DD];
__device__ bf16  g_h2h[ROWS*DD], g_h2l[ROWS*DD];
__device__ bf16  g_t1h[ROWS*RF], g_t1l[ROWS*RF];
__device__ bf16  g_gh [ROWS*DFF], g_gl[ROWS*DFF];
__device__ bf16  g_t2h[ROWS*RF], g_t2l[ROWS*RF];

__device__ __forceinline__ void bsplit(float a, bf16& h, bf16& l) {
    h = __float2bfloat16(a);
    l = __float2bfloat16(a - __bfloat162float(h));
}
__device__ __forceinline__ unsigned pack2(bf16 a, bf16 b) {
    __nv_bfloat162 t(a, b);
    return *(unsigned*)&t;
}
__device__ __forceinline__ float gelu_t(float x) {
    float t = 0.7978845608028654f * (x + 0.044715f * x * x * x);
    return 0.5f * x * (1.0f + tanhf(t));
}

// ---------------- layernorm -> bf16 hi/lo ----------------
__global__ __launch_bounds__(256) void ln_split(const float* __restrict__ x,
                                                const float* __restrict__ w,
                                                const float* __restrict__ b,
                                                bf16* __restrict__ oh,
                                                bf16* __restrict__ ol) {
    int row = blockIdx.x;
    const float* xr = x + (size_t)row * DD;
    float vals[3];
    float s = 0.f, s2 = 0.f;
    int tid = threadIdx.x;
#pragma unroll
    for (int i = 0; i < 3; i++) {
        float v = xr[tid + i * 256];
        vals[i] = v; s += v; s2 += v * v;
    }
    __shared__ float sh[256], sh2[256];
    sh[tid] = s; sh2[tid] = s2;
    __syncthreads();
    for (int off = 128; off > 0; off >>= 1) {
        if (tid < off) { sh[tid] += sh[tid + off]; sh2[tid] += sh2[tid + off]; }
        __syncthreads();
    }
    float mean = sh[0] * (1.0f / DD);
    float var  = sh2[0] * (1.0f / DD) - mean * mean;
    float rstd = rsqrtf(var + 1e-6f);
#pragma unroll
    for (int i = 0; i < 3; i++) {
        int c = tid + i * 256;
        float y = (vals[i] - mean) * rstd * w[c] + b[c];
        bsplit(y, oh[(size_t)row * DD + c], ol[(size_t)row * DD + c]);
    }
}

// ---------------- effective weight -> hi/lo ([k][n]) ----------------
__global__ __launch_bounds__(256) void weff_kernel(const float* __restrict__ Uq, const float* __restrict__ Vq,
                                                   const float* __restrict__ Uk, const float* __restrict__ Vk,
                                                   const float* __restrict__ Uv, const float* __restrict__ Vv,
                                                   bf16* __restrict__ wh, bf16* __restrict__ wl) {
    int idx = blockIdx.x * 256 + threadIdx.x;
    if (idx >= 3 * DD * DD) return;
    int which = idx / (DD * DD);
    int rem = idx % (DD * DD);
    int d = rem / DD, j = rem % DD;
    int hh = j >> 6, e = j & 63;
    const float* U = (which == 0) ? Uq : (which == 1) ? Uk : Uv;
    const float* V = (which == 0) ? Vq : (which == 1) ? Vk : Vv;
    const float* Uhd = U + ((size_t)hh * DD + d) * RA;
    const float* Vh  = V + (size_t)hh * RA * HDD + e;
    float acc = 0.f;
#pragma unroll
    for (int r = 0; r < RA; r++) acc += Uhd[r] * Vh[r * HDD];
    bsplit(acc, wh[idx], wl[idx]);
}

// ---------------- splits ----------------
__global__ __launch_bounds__(256) void split_kernel(const float* __restrict__ in,
                                                    bf16* __restrict__ oh, bf16* __restrict__ ol, int n) {
    int i = blockIdx.x * 256 + threadIdx.x;
    if (i < n) bsplit(in[i], oh[i], ol[i]);
}
__global__ __launch_bounds__(256) void wo_t_split(const float* __restrict__ Wo,
                                                  bf16* __restrict__ oh, bf16* __restrict__ ol) {
    int idx = blockIdx.x * 256 + threadIdx.x;
    if (idx >= DD * DD) return;
    int k = idx / DD, n = idx % DD;
    bsplit(Wo[(size_t)n * DD + k], oh[idx], ol[idx]);
}
// Vi [RF, 2*DFF] -> interleaved columns: out[k][2j] = Vi[k][j], out[k][2j+1] = Vi[k][DFF+j]
__global__ __launch_bounds__(256) void vi_perm_split(const float* __restrict__ Vi,
                                                     bf16* __restrict__ oh, bf16* __restrict__ ol) {
    int idx = blockIdx.x * 256 + threadIdx.x;
    if (idx >= RF * 2 * DFF) return;
    int k = idx / (2 * DFF), n = idx % (2 * DFF);
    int j = n >> 1;
    int srcn = (n & 1) ? (DFF + j) : j;
    bsplit(Vi[(size_t)k * (2 * DFF) + srcn], oh[idx], ol[idx]);
}

// ---------------- bf16x3 split tensor-core GEMM (wmma) ----------------
// C = (Ah+Al)@(Bh+Bl) ~ Ah*Bh + Ah*Bl + Al*Bh. A [M,K], B [K,N].
// OUTMODE: 0 fp32 (+bias,+res); 2 split hi/lo; 3 scatter split (+bias);
//          4 GEGLU (interleaved cols -> g split, bias indexed); 5 ROPE scatter split (+bias, scale)
template<int OUTMODE>
__global__ __launch_bounds__(256, 2) void gemm_bf3(
    const bf16* __restrict__ Agh, const bf16* __restrict__ Agl,
    const bf16* __restrict__ Bgh, const bf16* __restrict__ Bgl,
    const float* __restrict__ bias, const float* __restrict__ res,
    const float* __restrict__ cosT, const float* __restrict__ sinT, float scale,
    float* __restrict__ C, bf16* __restrict__ Ch, bf16* __restrict__ Cl,
    int M, int N, int K)
{
    extern __shared__ __align__(16) char smraw[];
    bf16* smb = (bf16*)smraw;
    int tid = threadIdx.x;
    int wid = tid >> 5;
    int warp_m = wid >> 2;   // 0..1
    int warp_n = wid & 3;    // 0..3
    int m0 = blockIdx.y * 128, n0 = blockIdx.x * 128;

    auto issue = [&](int c, int st) {
        int k0 = c * BK;
        bf16* sAh = smb + st * STAGE;
        bf16* sAl = sAh + A_TILE;
        bf16* sBh = sAl + A_TILE;
        bf16* sBl = sBh + B_TILE;
#pragma unroll
        for (int i = 0; i < 2; i++) {
            int t = tid + i * 256;           // 0..511
            int ar = t >> 2;                 // 0..127
            int ac = (t & 3) * 8;            // 0,8,16,24
            size_t ag = (size_t)(m0 + ar) * K + k0 + ac;
            __pipeline_memcpy_async(&sAh[ar * LDAs + ac], &Agh[ag], 16);
            __pipeline_memcpy_async(&sAl[ar * LDAs + ac], &Agl[ag], 16);
            int br = t >> 4;                 // 0..31
            int bc = (t & 15) * 8;           // 0..120
            size_t bg = (size_t)(k0 + br) * N + n0 + bc;
            __pipeline_memcpy_async(&sBh[br * LDBs + bc], &Bgh[bg], 16);
            __pipeline_memcpy_async(&sBl[br * LDBs + bc], &Bgl[bg], 16);
        }
    };

    wmma::fragment<wmma::accumulator, 16, 16, 16, float> cf[4][2];
#pragma unroll
    for (int i = 0; i < 4; i++)
#pragma unroll
        for (int j = 0; j < 2; j++) wmma::fill_fragment(cf[i][j], 0.0f);

    int nch = K / BK;
    issue(0, 0); __pipeline_commit();
    if (nch > 1) issue(1, 1);
    __pipeline_commit();

    for (int c = 0; c < nch; c++) {
        __pipeline_wait_prior(1);
        __syncthreads();
        int st = c & 1;
        bf16* sAh = smb + st * STAGE;
        bf16* sAl = sAh + A_TILE;
        bf16* sBh = sAl + A_TILE;
        bf16* sBl = sBh + B_TILE;
#pragma unroll
        for (int ks = 0; ks < 2; ks++) {
            wmma::fragment<wmma::matrix_b, 16, 16, 16, bf16, wmma::row_major> bh[2], bl[2];
#pragma unroll
            for (int j = 0; j < 2; j++) {
                wmma::load_matrix_sync(bh[j], &sBh[(ks * 16) * LDBs + warp_n * 32 + j * 16], LDBs);
                wmma::load_matrix_sync(bl[j], &sBl[(ks * 16) * LDBs + warp_n * 32 + j * 16], LDBs);
            }
#pragma unroll
            for (int i = 0; i < 4; i++) {
                wmma::fragment<wmma::matrix_a, 16, 16, 16, bf16, wmma::row_major> ah, al;
                wmma::load_matrix_sync(ah, &sAh[(warp_m * 64 + i * 16) * LDAs + ks * 16], LDAs);
                wmma::load_matrix_sync(al, &sAl[(warp_m * 64 + i * 16) * LDAs + ks * 16], LDAs);
#pragma unroll
                for (int j = 0; j < 2; j++) {
                    wmma::mma_sync(cf[i][j], ah, bh[j], cf[i][j]);
                    wmma::mma_sync(cf[i][j], ah, bl[j], cf[i][j]);
                    wmma::mma_sync(cf[i][j], al, bh[j], cf[i][j]);
                }
            }
        }
        __syncthreads();
        if (c + 2 < nch) issue(c + 2, st);
        __pipeline_commit();
    }

    // ---- epilogue: frags -> smem fp32 -> global ----
    float* Csm = (float*)smraw;
#pragma unroll
    for (int i = 0; i < 4; i++)
#pragma unroll
        for (int j = 0; j < 2; j++)
            wmma::store_matrix_sync(&Csm[(warp_m * 64 + i * 16) * LDC + warp_n * 32 + j * 16],
                                    cf[i][j], LDC, wmma::mem_row_major);
    __syncthreads();

#pragma unroll
    for (int it = 0; it < 16; it++) {
        int idx = tid + it * 256;        // 4096 float4
        int r = idx >> 5;                // 0..127
        int c4 = (idx & 31) << 2;        // 0..124
        float4 v = *(const float4*)&Csm[r * LDC + c4];
        int m = m0 + r, n = n0 + c4;
        if (OUTMODE <= 3) {
            if (bias) {
                float4 bb = *(const float4*)&bias[n];
                v.x += bb.x; v.y += bb.y; v.z += bb.z; v.w += bb.w;
            }
            if (res) {
                float4 rr = *(const float4*)&res[(size_t)m * N + n];
                v.x += rr.x; v.y += rr.y; v.z += rr.z; v.w += rr.w;
            }
        }
        if (OUTMODE == 0) {
            *(float4*)&C[(size_t)m * N + n] = v;
        } else if (OUTMODE == 2) {
            bf16 hv[4], lv[4];
            bsplit(v.x, hv[0], lv[0]); bsplit(v.y, hv[1], lv[1]);
            bsplit(v.z, hv[2], lv[2]); bsplit(v.w, hv[3], lv[3]);
            *(uint2*)&Ch[(size_t)m * N + n] = *(uint2*)hv;
            *(uint2*)&Cl[(size_t)m * N + n] = *(uint2*)lv;
        } else if (OUTMODE == 3) {
            int b = m >> 11, s = m & 2047, head = n >> 6, e = n & 63;
            size_t o = (((size_t)b * HH + head) * SS + s) * HDD + e;
            bf16 hv[4], lv[4];
            bsplit(v.x, hv[0], lv[0]); bsplit(v.y, hv[1], lv[1]);
            bsplit(v.z, hv[2], lv[2]); bsplit(v.w, hv[3], lv[3]);
            *(uint2*)&Ch[o] = *(uint2*)hv;
            *(uint2*)&Cl[o] = *(uint2*)lv;
        } else if (OUTMODE == 4) {
            // columns interleaved (g1,g2): even n -> g1[j=n/2], odd -> g2[j]
            int j0 = n >> 1;             // first pair index
            float g1a = v.x + bias[j0];
            float g2a = v.y + bias[DFF + j0];
            float g1b = v.z + bias[j0 + 1];
            float g2b = v.w + bias[DFF + j0 + 1];
            float ga = gelu_t(g1a) * g2a;
            float gb = gelu_t(g1b) * g2b;
            bf16 h0, l0, h1, l1;
            bsplit(ga, h0, l0); bsplit(gb, h1, l1);
            size_t o = (size_t)m * DFF + j0;
            *(unsigned*)&Ch[o] = pack2(h0, h1);
            *(unsigned*)&Cl[o] = pack2(l0, l1);
        } else {  // OUTMODE == 5: rope + scale + scatter split
            int e = n & 63;
            float4 p = *(const float4*)&Csm[r * LDC + (c4 ^ 32)];
            {
                float4 bb = *(const float4*)&bias[n];
                v.x += bb.x; v.y += bb.y; v.z += bb.z; v.w += bb.w;
                float4 pb = *(const float4*)&bias[n ^ 32];
                p.x += pb.x; p.y += pb.y; p.z += pb.z; p.w += pb.w;
            }
            int s = m & 2047;
            float4 cs = *(const float4*)&cosT[s * HDD + e];
            float4 sn = *(const float4*)&sinT[s * HDD + e];
            float4 o4;
            if (e < 32) {
                o4.x = v.x * cs.x - p.x * sn.x; o4.y = v.y * cs.y - p.y * sn.y;
                o4.z = v.z * cs.z - p.z * sn.z; o4.w = v.w * cs.w - p.w * sn.w;
            } else {
                o4.x = v.x * cs.x + p.x * sn.x; o4.y = v.y * cs.y + p.y * sn.y;
                o4.z = v.z * cs.z + p.z * sn.z; o4.w = v.w * cs.w + p.w * sn.w;
            }
            o4.x *= scale; o4.y *= scale; o4.z *= scale; o4.w *= scale;
            int b = m >> 11, head = n >> 6;
            size_t o = (((size_t)b * HH + head) * SS + s) * HDD + e;
            bf16 hv[4], lv[4];
            bsplit(o4.x, hv[0], lv[0]); bsplit(o4.y, hv[1], lv[1]);
            bsplit(o4.z, hv[2], lv[2]); bsplit(o4.w, hv[3], lv[3]);
            *(uint2*)&Ch[o] = *(uint2*)hv;
            *(uint2*)&Cl[o] = *(uint2*)lv;
        }
    }
}

// ---------------- tensor-core flash attention (bf16x3, wmma) ----------------
#define LDQ 72
#define LDKV 72
#define LDP 72
#define LDSS 68
#define LDO 68
__global__ __launch_bounds__(256, 1) void attn_tc(
    const bf16* __restrict__ Qh_, const bf16* __restrict__ Ql_,
    const bf16* __restrict__ Kh_, const bf16* __restrict__ Kl_,
    const bf16* __restrict__ Vh_, const bf16* __restrict__ Vl_,
    bf16* __restrict__ Oh_, bf16* __restrict__ Ol_)
{
    extern __shared__ __align__(16) char smraw_[];
    bf16* sQh = (bf16*)smraw_;
    bf16* sQl = sQh + 128 * LDQ;
    bf16* sKh = sQl + 128 * LDQ;
    bf16* sKl = sKh + 64 * LDKV;
    bf16* sVh = sKl + 64 * LDKV;
    bf16* sVl = sVh + 64 * LDKV;
    bf16* sPh = sVl + 64 * LDKV;
    bf16* sPl = sPh + 128 * LDP;
    float* sS = (float*)(sPl + 128 * LDP);
    float* sO = sS + 128 * LDSS;

    int tid = threadIdx.x;
    int warp = tid >> 5;
    int bh = blockIdx.y;
    int q0 = blockIdx.x * 128;
    size_t qoff = ((size_t)bh * SS + q0) * HDD;

#pragma unroll
    for (int i = 0; i < 4; i++) {
        int idx = tid + i * 256;
        int r = idx >> 3, c8 = (idx & 7) * 8;
        *(uint4*)&sQh[r * LDQ + c8] = *(const uint4*)&Qh_[qoff + (size_t)r * HDD + c8];
        *(uint4*)&sQl[r * LDQ + c8] = *(const uint4*)&Ql_[qoff + (size_t)r * HDD + c8];
    }
#pragma unroll
    for (int i = 0; i < 34; i++) sO[tid + i * 256] = 0.f;

    float m = -1e30f, l = 0.f;
    int r = tid >> 1, c0 = (tid & 1) * 32;

    for (int kc0 = 0; kc0 < SS; kc0 += 64) {
        __syncthreads();
        size_t koff = ((size_t)bh * SS + kc0) * HDD;
#pragma unroll
        for (int i = 0; i < 2; i++) {
            int idx = tid + i * 256;
            int rr = idx >> 3, c8 = (idx & 7) * 8;
            *(uint4*)&sKh[rr * LDKV + c8] = *(const uint4*)&Kh_[koff + (size_t)rr * HDD + c8];
            *(uint4*)&sKl[rr * LDKV + c8] = *(const uint4*)&Kl_[koff + (size_t)rr * HDD + c8];
            *(uint4*)&sVh[rr * LDKV + c8] = *(const uint4*)&Vh_[koff + (size_t)rr * HDD + c8];
            *(uint4*)&sVl[rr * LDKV + c8] = *(const uint4*)&Vl_[koff + (size_t)rr * HDD + c8];
        }
        __syncthreads();

        {
            wmma::fragment<wmma::accumulator, 16, 16, 16, float> sf[4];
#pragma unroll
            for (int j = 0; j < 4; j++) wmma::fill_fragment(sf[j], 0.f);
#pragma unroll
            for (int ks = 0; ks < 4; ks++) {
                wmma::fragment<wmma::matrix_a, 16, 16, 16, bf16, wmma::row_major> ah, al;
                wmma::load_matrix_sync(ah, &sQh[(warp * 16) * LDQ + ks * 16], LDQ);
                wmma::load_matrix_sync(al, &sQl[(warp * 16) * LDQ + ks * 16], LDQ);
#pragma unroll
                for (int j = 0; j < 4; j++) {
                    wmma::fragment<wmma::matrix_b, 16, 16, 16, bf16, wmma::col_major> bhf, blf;
                    wmma::load_matrix_sync(bhf, &sKh[(j * 16) * LDKV + ks * 16], LDKV);
                    wmma::load_matrix_sync(blf, &sKl[(j * 16) * LDKV + ks * 16], LDKV);
                    wmma::mma_sync(sf[j], ah, bhf, sf[j]);
                    wmma::mma_sync(sf[j], ah, blf, sf[j]);
                    wmma::mma_sync(sf[j], al, bhf, sf[j]);
                }
            }
#pragma unroll
            for (int j = 0; j < 4; j++)
                wmma::store_matrix_sync(&sS[(warp * 16) * LDSS + j * 16], sf[j], LDSS, wmma::mem_row_major);
        }
        __syncthreads();

        {
            const float* srow = sS + r * LDSS + c0;
            float tmax = -1e30f;
#pragma unroll
            for (int cc = 0; cc < 8; cc++) {
                float4 sv = *(const float4*)&srow[cc * 4];
                tmax = fmaxf(tmax, fmaxf(fmaxf(sv.x, sv.y), fmaxf(sv.z, sv.w)));
            }
            tmax = fmaxf(tmax, __shfl_xor_sync(0xffffffffu, tmax, 1));
            float mnew = fmaxf(m, tmax);
            float corr = __expf(m - mnew);
            float sum = 0.f;
            unsigned* ph = (unsigned*)&sPh[r * LDP + c0];
            unsigned* pl = (unsigned*)&sPl[r * LDP + c0];
#pragma unroll
            for (int cc = 0; cc < 8; cc++) {
                float4 sv = *(const float4*)&srow[cc * 4];
                float p0 = __expf(sv.x - mnew), p1 = __expf(sv.y - mnew);
                float p2 = __expf(sv.z - mnew), p3 = __expf(sv.w - mnew);
                sum += (p0 + p1) + (p2 + p3);
                bf16 h0, l0, h1, l1, h2, l2, h3, l3;
                bsplit(p0, h0, l0); bsplit(p1, h1, l1);
                bsplit(p2, h2, l2); bsplit(p3, h3, l3);
                uint2 uh = { pack2(h0, h1), pack2(h2, h3) };
                uint2 ul = { pack2(l0, l1), pack2(l2, l3) };
                *(uint2*)&ph[cc * 2] = uh;
                *(uint2*)&pl[cc * 2] = ul;
            }
            sum += __shfl_xor_sync(0xffffffffu, sum, 1);
            l = l * corr + sum;
            m = mnew;
            float* orow = sO + r * LDO + c0;
#pragma unroll
            for (int cc = 0; cc < 8; cc++) {
                float4 ov = *(const float4*)&orow[cc * 4];
                ov.x *= corr; ov.y *= corr; ov.z *= corr; ov.w *= corr;
                *(float4*)&orow[cc * 4] = ov;
            }
        }
        __syncthreads();

        {
            wmma::fragment<wmma::matrix_a, 16, 16, 16, bf16, wmma::row_major> pah[4], pal[4];
#pragma unroll
            for (int ks = 0; ks < 4; ks++) {
                wmma::load_matrix_sync(pah[ks], &sPh[(warp * 16) * LDP + ks * 16], LDP);
                wmma::load_matrix_sync(pal[ks], &sPl[(warp * 16) * LDP + ks * 16], LDP);
            }
#pragma unroll
            for (int j = 0; j < 4; j++) {
                wmma::fragment<wmma::accumulator, 16, 16, 16, float> of;
                wmma::load_matrix_sync(of, &sO[(warp * 16) * LDO + j * 16], LDO, wmma::mem_row_major);
#pragma unroll
                for (int ks = 0; ks < 4; ks++) {
                    wmma::fragment<wmma::matrix_b, 16, 16, 16, bf16, wmma::row_major> vbh, vbl;
                    wmma::load_matrix_sync(vbh, &sVh[(ks * 16) * LDKV + j * 16], LDKV);
                    wmma::load_matrix_sync(vbl, &sVl[(ks * 16) * LDKV + j * 16], LDKV);
                    wmma::mma_sync(of, pah[ks], vbh, of);
                    wmma::mma_sync(of, pal[ks], vbh, of);
                    wmma::mma_sync(of, pah[ks], vbl, of);
                }
                wmma::store_matrix_sync(&sO[(warp * 16) * LDO + j * 16], of, LDO, wmma::mem_row_major);
            }
        }
    }
    __syncthreads();

    int b = bh / HH, hd = bh % HH;
    float inv = 1.0f / l;
    size_t obase = ((size_t)(b * SS + q0 + r)) * DD + hd * HDD + c0;
    const float* orow = sO + r * LDO + c0;
#pragma unroll
    for (int cc = 0; cc < 8; cc++) {
        float4 ov = *(const float4*)&orow[cc * 4];
        bf16 h0, l0, h1, l1, h2, l2, h3, l3;
        bsplit(ov.x * inv, h0, l0); bsplit(ov.y * inv, h1, l1);
        bsplit(ov.z * inv, h2, l2); bsplit(ov.w * inv, h3, l3);
        uint2 uh = { pack2(h0, h1), pack2(h2, h3) };
        uint2 ul = { pack2(l0, l1), pack2(l2, l3) };
        *(uint2*)&Oh_[obase + cc * 4] = uh;
        *(uint2*)&Ol_[obase + cc * 4] = ul;
    }
}

// ---------------- launch ----------------
extern "C" void kernel_launch(void* const* d_in, const int* in_sizes, int n_in,
                              void* d_out, int out_size) {
    const float* x    = (const float*)d_in[0];
    const float* anw  = (const float*)d_in[1];
    const float* anb  = (const float*)d_in[2];
    const float* Uq   = (const float*)d_in[3];
    const float* Vq   = (const float*)d_in[4];
    const float* bq   = (const float*)d_in[5];
    const float* Uk   = (const float*)d_in[6];
    const float* Vk   = (const float*)d_in[7];
    const float* bk   = (const float*)d_in[8];
    const float* Uv   = (const float*)d_in[9];
    const float* Vv   = (const float*)d_in[10];
    const float* bv   = (const float*)d_in[11];
    const float* Wo_w = (const float*)d_in[12];
    const float* Wo_b = (const float*)d_in[13];
    const float* mnw  = (const float*)d_in[14];
    const float* mnb  = (const float*)d_in[15];
    const float* Ui   = (const float*)d_in[16];
    const float* Vi   = (const float*)d_in[17];
    const float* bi   = (const float*)d_in[18];
    const float* Uo   = (const float*)d_in[19];
    const float* Vo   = (const float*)d_in[20];
    const float* bo   = (const float*)d_in[21];
    const float* cosT = (const float*)d_in[22];
    const float* sinT = (const float*)d_in[23];
    float* out = (float*)d_out;

    bf16 *hh,*hl,*weffh,*weffl,*woth,*wotl,*uih,*uil,*vih,*vil,*uoh,*uol,*voh,*vol;
    bf16 *qh,*ql,*kh,*kl,*vh,*vl,*oh,*ol,*h2h,*h2l,*t1h,*t1l,*gh,*gl,*t2h,*t2l;
    float *x1;
    cudaGetSymbolAddress((void**)&hh, g_hh);   cudaGetSymbolAddress((void**)&hl, g_hl);
    cudaGetSymbolAddress((void**)&weffh, g_weffh); cudaGetSymbolAddress((void**)&weffl, g_weffl);
    cudaGetSymbolAddress((void**)&woth, g_woth);   cudaGetSymbolAddress((void**)&wotl, g_wotl);
    cudaGetSymbolAddress((void**)&uih, g_uih); cudaGetSymbolAddress((void**)&uil, g_uil);
    cudaGetSymbolAddress((void**)&vih, g_vih); cudaGetSymbolAddress((void**)&vil, g_vil);
    cudaGetSymbolAddress((void**)&uoh, g_uoh); cudaGetSymbolAddress((void**)&uol, g_uol);
    cudaGetSymbolAddress((void**)&voh, g_voh); cudaGetSymbolAddress((void**)&vol, g_vol);
    cudaGetSymbolAddress((void**)&qh, g_qh); cudaGetSymbolAddress((void**)&ql, g_ql);
    cudaGetSymbolAddress((void**)&kh, g_kh); cudaGetSymbolAddress((void**)&kl, g_kl);
    cudaGetSymbolAddress((void**)&vh, g_vh); cudaGetSymbolAddress((void**)&vl, g_vl);
    cudaGetSymbolAddress((void**)&oh, g_oh); cudaGetSymbolAddress((void**)&ol, g_ol);
    cudaGetSymbolAddress((void**)&x1, g_x1);
    cudaGetSymbolAddress((void**)&h2h, g_h2h); cudaGetSymbolAddress((void**)&h2l, g_h2l);
    cudaGetSymbolAddress((void**)&t1h, g_t1h); cudaGetSymbolAddress((void**)&t1l, g_t1l);
    cudaGetSymbolAddress((void**)&gh, g_gh); cudaGetSymbolAddress((void**)&gl, g_gl);
    cudaGetSymbolAddress((void**)&t2h, g_t2h); cudaGetSymbolAddress((void**)&t2l, g_t2l);

    const int att_smem = 180224;
    cudaFuncSetAttribute(attn_tc, cudaFuncAttributeMaxDynamicSharedMemorySize, att_smem);
    cudaFuncSetAttribute(gemm_bf3<0>, cudaFuncAttributeMaxDynamicSharedMemorySize, GEMM_SMEM);
    cudaFuncSetAttribute(gemm_bf3<2>, cudaFuncAttributeMaxDynamicSharedMemorySize, GEMM_SMEM);
    cudaFuncSetAttribute(gemm_bf3<3>, cudaFuncAttributeMaxDynamicSharedMemorySize, GEMM_SMEM);
    cudaFuncSetAttribute(gemm_bf3<4>, cudaFuncAttributeMaxDynamicSharedMemorySize, GEMM_SMEM);
    cudaFuncSetAttribute(gemm_bf3<5>, cudaFuncAttributeMaxDynamicSharedMemorySize, GEMM_SMEM);

    // 1. LN1
    ln_split<<<ROWS, 256>>>(x, anw, anb, hh, hl);
    // 2. weights -> hi/lo
    weff_kernel<<<(3 * DD * DD + 255) / 256, 256>>>(Uq, Vq, Uk, Vk, Uv, Vv, weffh, weffl);
    wo_t_split<<<(DD * DD + 255) / 256, 256>>>(Wo_w, woth, wotl);
    split_kernel<<<(DD * RF + 255) / 256, 256>>>(Ui, uih, uil, DD * RF);
    vi_perm_split<<<(RF * 2 * DFF + 255) / 256, 256>>>(Vi, vih, vil);
    split_kernel<<<(DFF * RF + 255) / 256, 256>>>(Uo, uoh, uol, DFF * RF);
    split_kernel<<<(RF * DD + 255) / 256, 256>>>(Vo, voh, vol, RF * DD);
    // 3. Q/K with fused rope+scale+split, V scatter+split
    dim3 gQKV(DD / 128, ROWS / 128);
    gemm_bf3<5><<<gQKV, 256, GEMM_SMEM>>>(hh, hl, weffh,           weffl,           bq, nullptr, cosT, sinT, 0.125f, nullptr, qh, ql, ROWS, DD, DD);
    gemm_bf3<5><<<gQKV, 256, GEMM_SMEM>>>(hh, hl, weffh + DD * DD, weffl + DD * DD, bk, nullptr, cosT, sinT, 1.0f,   nullptr, kh, kl, ROWS, DD, DD);
    gemm_bf3<3><<<gQKV, 256, GEMM_SMEM>>>(hh, hl, weffh + 2*DD*DD, weffl + 2*DD*DD, bv, nullptr, nullptr, nullptr, 1.f, nullptr, vh, vl, ROWS, DD, DD);
    // 4. tensor-core attention
    attn_tc<<<dim3(SS / 128, BB * HH), 256, att_smem>>>(qh, ql, kh, kl, vh, vl, oh, ol);
    // 5. x1 = x + o @ Wo^T + Wo_b
    gemm_bf3<0><<<dim3(DD / 128, ROWS / 128), 256, GEMM_SMEM>>>(oh, ol, woth, wotl, Wo_b, x, nullptr, nullptr, 1.f, x1, nullptr, nullptr, ROWS, DD, DD);
    // 6. LN2
    ln_split<<<ROWS, 256>>>(x1, mnw, mnb, h2h, h2l);
    // 7. t1 = h2 @ Ui
    gemm_bf3<2><<<dim3(RF / 128, ROWS / 128), 256, GEMM_SMEM>>>(h2h, h2l, uih, uil, nullptr, nullptr, nullptr, nullptr, 1.f, nullptr, t1h, t1l, ROWS, RF, DD);
    // 8. g = GEGLU(t1 @ ViP + biP) fused
    gemm_bf3<4><<<dim3(2 * DFF / 128, ROWS / 128), 256, GEMM_SMEM>>>(t1h, t1l, vih, vil, bi, nullptr, nullptr, nullptr, 1.f, nullptr, gh, gl, ROWS, 2 * DFF, RF);
    // 9. t2 = g @ Uo
    gemm_bf3<2><<<dim3(RF / 128, ROWS / 128), 256, GEMM_SMEM>>>(gh, gl, uoh, uol, nullptr, nullptr, nullptr, nullptr, 1.f, nullptr, t2h, t2l, ROWS, RF, DFF);
    // 10. out = x1 + t2 @ Vo + bo
    gemm_bf3<0><<<dim3(DD / 128, ROWS / 128), 256, GEMM_SMEM>>>(t2h, t2l, voh, vol, bo, x1, nullptr, nullptr, 1.f, out, nullptr, nullptr, ROWS, DD, RF);
}

// round 8
// speedup vs baseline: 3.0382x; 1.1226x over previous
#include <cuda_runtime.h>
#include <cuda_bf16.h>
#include <cuda_pipeline.h>
#include <mma.h>
#include <math.h>
#include <cstdint>

using namespace nvcuda;

// ---------------- problem constants ----------------
#define BB 4
#define SS 2048
#define DD 768
#define HH 12
#define HDD 64
#define RA 32
#define RF 512
#define DFF 3072
#define ROWS (BB*SS)          // 8192

// ---------------- GEMM tile constants ----------------
#define BK 32
#define LDAs 40               // bf16 elems (80B rows, 16B aligned)
#define LDBs 136              // bf16 elems (272B rows)
#define A_TILE (128*LDAs)     // 5120
#define B_TILE (BK*LDBs)      // 4352
#define STAGE (2*A_TILE + 2*B_TILE)   // 18944 bf16
#define GEMM_SMEM (2*STAGE*2)         // 75776 bytes
#define LDC 132               // Csm floats: 128*132*4 = 67584 <= 75776

typedef __nv_bfloat16 bf16;

// ---------------- scratch ----------------
__device__ bf16  g_hh [ROWS*DD];
__device__ bf16  g_hl [ROWS*DD];
__device__ bf16  g_weffh[3*DD*DD];     // [which][k][n]
__device__ bf16  g_weffl[3*DD*DD];
__device__ bf16  g_woth[DD*DD];        // Wo^T [k][n]
__device__ bf16  g_wotl[DD*DD];
__device__ bf16  g_uih[DD*RF],  g_uil[DD*RF];
__device__ bf16  g_vih[RF*2*DFF], g_vil[RF*2*DFF];    // column-interleaved (g1,g2 pairs)
__device__ bf16  g_uoh[DFF*RF], g_uol[DFF*RF];
__device__ bf16  g_voh[RF*DD],  g_vol[RF*DD];
__device__ bf16  g_qh [ROWS*DD], g_ql[ROWS*DD];   // [B,H,S,HD] post-rope, q scaled
__device__ bf16  g_kh [ROWS*DD], g_kl[ROWS*DD];
__device__ bf16  g_vh [ROWS*DD], g_vl[ROWS*DD];
__device__ bf16  g_oh [ROWS*DD], g_ol[ROWS*DD];
__device__ float g_x1 [ROWS*DD];
__device__ bf16  g_h2h[ROWS*DD], g_h2l[ROWS*DD];
__device__ bf16  g_t1h[ROWS*RF], g_t1l[ROWS*RF];
__device__ bf16  g_gh [ROWS*DFF], g_gl[ROWS*DFF];
__device__ bf16  g_t2h[ROWS*RF], g_t2l[ROWS*RF];

__device__ __forceinline__ void bsplit(float a, bf16& h, bf16& l) {
    h = __float2bfloat16(a);
    l = __float2bfloat16(a - __bfloat162float(h));
}
__device__ __forceinline__ unsigned pack2(bf16 a, bf16 b) {
    __nv_bfloat162 t(a, b);
    return *(unsigned*)&t;
}
__device__ __forceinline__ float gelu_t(float x) {
    float t = 0.7978845608028654f * (x + 0.044715f * x * x * x);
    return 0.5f * x * (1.0f + tanhf(t));
}

// ---------------- layernorm -> bf16 hi/lo ----------------
__global__ __launch_bounds__(256) void ln_split(const float* __restrict__ x,
                                                const float* __restrict__ w,
                                                const float* __restrict__ b,
                                                bf16* __restrict__ oh,
                                                bf16* __restrict__ ol) {
    int row = blockIdx.x;
    const float* xr = x + (size_t)row * DD;
    float vals[3];
    float s = 0.f, s2 = 0.f;
    int tid = threadIdx.x;
#pragma unroll
    for (int i = 0; i < 3; i++) {
        float v = xr[tid + i * 256];
        vals[i] = v; s += v; s2 += v * v;
    }
    __shared__ float sh[256], sh2[256];
    sh[tid] = s; sh2[tid] = s2;
    __syncthreads();
    for (int off = 128; off > 0; off >>= 1) {
        if (tid < off) { sh[tid] += sh[tid + off]; sh2[tid] += sh2[tid + off]; }
        __syncthreads();
    }
    float mean = sh[0] * (1.0f / DD);
    float var  = sh2[0] * (1.0f / DD) - mean * mean;
    float rstd = rsqrtf(var + 1e-6f);
#pragma unroll
    for (int i = 0; i < 3; i++) {
        int c = tid + i * 256;
        float y = (vals[i] - mean) * rstd * w[c] + b[c];
        bsplit(y, oh[(size_t)row * DD + c], ol[(size_t)row * DD + c]);
    }
}

// ---------------- effective weight -> hi/lo ([k][n]) ----------------
__global__ __launch_bounds__(256) void weff_kernel(const float* __restrict__ Uq, const float* __restrict__ Vq,
                                                   const float* __restrict__ Uk, const float* __restrict__ Vk,
                                                   const float* __restrict__ Uv, const float* __restrict__ Vv,
                                                   bf16* __restrict__ wh, bf16* __restrict__ wl) {
    int idx = blockIdx.x * 256 + threadIdx.x;
    if (idx >= 3 * DD * DD) return;
    int which = idx / (DD * DD);
    int rem = idx % (DD * DD);
    int d = rem / DD, j = rem % DD;
    int hh = j >> 6, e = j & 63;
    const float* U = (which == 0) ? Uq : (which == 1) ? Uk : Uv;
    const float* V = (which == 0) ? Vq : (which == 1) ? Vk : Vv;
    const float* Uhd = U + ((size_t)hh * DD + d) * RA;
    const float* Vh  = V + (size_t)hh * RA * HDD + e;
    float acc = 0.f;
#pragma unroll
    for (int r = 0; r < RA; r++) acc += Uhd[r] * Vh[r * HDD];
    bsplit(acc, wh[idx], wl[idx]);
}

// ---------------- splits ----------------
__global__ __launch_bounds__(256) void split_kernel(const float* __restrict__ in,
                                                    bf16* __restrict__ oh, bf16* __restrict__ ol, int n) {
    int i = blockIdx.x * 256 + threadIdx.x;
    if (i < n) bsplit(in[i], oh[i], ol[i]);
}
__global__ __launch_bounds__(256) void wo_t_split(const float* __restrict__ Wo,
                                                  bf16* __restrict__ oh, bf16* __restrict__ ol) {
    int idx = blockIdx.x * 256 + threadIdx.x;
    if (idx >= DD * DD) return;
    int k = idx / DD, n = idx % DD;
    bsplit(Wo[(size_t)n * DD + k], oh[idx], ol[idx]);
}
// Vi [RF, 2*DFF] -> interleaved columns: out[k][2j] = Vi[k][j], out[k][2j+1] = Vi[k][DFF+j]
__global__ __launch_bounds__(256) void vi_perm_split(const float* __restrict__ Vi,
                                                     bf16* __restrict__ oh, bf16* __restrict__ ol) {
    int idx = blockIdx.x * 256 + threadIdx.x;
    if (idx >= RF * 2 * DFF) return;
    int k = idx / (2 * DFF), n = idx % (2 * DFF);
    int j = n >> 1;
    int srcn = (n & 1) ? (DFF + j) : j;
    bsplit(Vi[(size_t)k * (2 * DFF) + srcn], oh[idx], ol[idx]);
}

// ---------------- bf16x3 split tensor-core GEMM (wmma) ----------------
// C = (Ah+Al)@(Bh+Bl) ~ Ah*Bh + Ah*Bl + Al*Bh. A [M,K], B [K,N].
// OUTMODE: 0 fp32 (+bias,+res); 2 split hi/lo; 3 scatter split (+bias);
//          4 GEGLU; 5 ROPE scatter split (+bias, scale)
template<int OUTMODE>
__global__ __launch_bounds__(256, 2) void gemm_bf3(
    const bf16* __restrict__ Agh, const bf16* __restrict__ Agl,
    const bf16* __restrict__ Bgh, const bf16* __restrict__ Bgl,
    const float* __restrict__ bias, const float* __restrict__ res,
    const float* __restrict__ cosT, const float* __restrict__ sinT, float scale,
    float* __restrict__ C, bf16* __restrict__ Ch, bf16* __restrict__ Cl,
    int M, int N, int K)
{
    extern __shared__ __align__(16) char smraw[];
    bf16* smb = (bf16*)smraw;
    int tid = threadIdx.x;
    int wid = tid >> 5;
    int warp_m = wid >> 2;   // 0..1
    int warp_n = wid & 3;    // 0..3
    int m0 = blockIdx.y * 128, n0 = blockIdx.x * 128;

    auto issue = [&](int c, int st) {
        int k0 = c * BK;
        bf16* sAh = smb + st * STAGE;
        bf16* sAl = sAh + A_TILE;
        bf16* sBh = sAl + A_TILE;
        bf16* sBl = sBh + B_TILE;
#pragma unroll
        for (int i = 0; i < 2; i++) {
            int t = tid + i * 256;           // 0..511
            int ar = t >> 2;                 // 0..127
            int ac = (t & 3) * 8;            // 0,8,16,24
            size_t ag = (size_t)(m0 + ar) * K + k0 + ac;
            __pipeline_memcpy_async(&sAh[ar * LDAs + ac], &Agh[ag], 16);
            __pipeline_memcpy_async(&sAl[ar * LDAs + ac], &Agl[ag], 16);
            int br = t >> 4;                 // 0..31
            int bc = (t & 15) * 8;           // 0..120
            size_t bg = (size_t)(k0 + br) * N + n0 + bc;
            __pipeline_memcpy_async(&sBh[br * LDBs + bc], &Bgh[bg], 16);
            __pipeline_memcpy_async(&sBl[br * LDBs + bc], &Bgl[bg], 16);
        }
    };

    wmma::fragment<wmma::accumulator, 16, 16, 16, float> cf[4][2];
#pragma unroll
    for (int i = 0; i < 4; i++)
#pragma unroll
        for (int j = 0; j < 2; j++) wmma::fill_fragment(cf[i][j], 0.0f);

    int nch = K / BK;
    issue(0, 0); __pipeline_commit();
    if (nch > 1) issue(1, 1);
    __pipeline_commit();

    for (int c = 0; c < nch; c++) {
        __pipeline_wait_prior(1);
        __syncthreads();
        int st = c & 1;
        bf16* sAh = smb + st * STAGE;
        bf16* sAl = sAh + A_TILE;
        bf16* sBh = sAl + A_TILE;
        bf16* sBl = sBh + B_TILE;
#pragma unroll
        for (int ks = 0; ks < 2; ks++) {
            wmma::fragment<wmma::matrix_b, 16, 16, 16, bf16, wmma::row_major> bh[2], bl[2];
#pragma unroll
            for (int j = 0; j < 2; j++) {
                wmma::load_matrix_sync(bh[j], &sBh[(ks * 16) * LDBs + warp_n * 32 + j * 16], LDBs);
                wmma::load_matrix_sync(bl[j], &sBl[(ks * 16) * LDBs + warp_n * 32 + j * 16], LDBs);
            }
#pragma unroll
            for (int i = 0; i < 4; i++) {
                wmma::fragment<wmma::matrix_a, 16, 16, 16, bf16, wmma::row_major> ah, al;
                wmma::load_matrix_sync(ah, &sAh[(warp_m * 64 + i * 16) * LDAs + ks * 16], LDAs);
                wmma::load_matrix_sync(al, &sAl[(warp_m * 64 + i * 16) * LDAs + ks * 16], LDAs);
#pragma unroll
                for (int j = 0; j < 2; j++) {
                    wmma::mma_sync(cf[i][j], ah, bh[j], cf[i][j]);
                    wmma::mma_sync(cf[i][j], ah, bl[j], cf[i][j]);
                    wmma::mma_sync(cf[i][j], al, bh[j], cf[i][j]);
                }
            }
        }
        __syncthreads();
        if (c + 2 < nch) issue(c + 2, st);
        __pipeline_commit();
    }

    // ---- epilogue: frags -> smem fp32 -> global ----
    float* Csm = (float*)smraw;
#pragma unroll
    for (int i = 0; i < 4; i++)
#pragma unroll
        for (int j = 0; j < 2; j++)
            wmma::store_matrix_sync(&Csm[(warp_m * 64 + i * 16) * LDC + warp_n * 32 + j * 16],
                                    cf[i][j], LDC, wmma::mem_row_major);
    __syncthreads();

#pragma unroll
    for (int it = 0; it < 16; it++) {
        int idx = tid + it * 256;        // 4096 float4
        int r = idx >> 5;                // 0..127
        int c4 = (idx & 31) << 2;        // 0..124
        float4 v = *(const float4*)&Csm[r * LDC + c4];
        int m = m0 + r, n = n0 + c4;
        if (OUTMODE <= 3) {
            if (bias) {
                float4 bb = *(const float4*)&bias[n];
                v.x += bb.x; v.y += bb.y; v.z += bb.z; v.w += bb.w;
            }
            if (res) {
                float4 rr = *(const float4*)&res[(size_t)m * N + n];
                v.x += rr.x; v.y += rr.y; v.z += rr.z; v.w += rr.w;
            }
        }
        if (OUTMODE == 0) {
            *(float4*)&C[(size_t)m * N + n] = v;
        } else if (OUTMODE == 2) {
            bf16 hv[4], lv[4];
            bsplit(v.x, hv[0], lv[0]); bsplit(v.y, hv[1], lv[1]);
            bsplit(v.z, hv[2], lv[2]); bsplit(v.w, hv[3], lv[3]);
            *(uint2*)&Ch[(size_t)m * N + n] = *(uint2*)hv;
            *(uint2*)&Cl[(size_t)m * N + n] = *(uint2*)lv;
        } else if (OUTMODE == 3) {
            int b = m >> 11, s = m & 2047, head = n >> 6, e = n & 63;
            size_t o = (((size_t)b * HH + head) * SS + s) * HDD + e;
            bf16 hv[4], lv[4];
            bsplit(v.x, hv[0], lv[0]); bsplit(v.y, hv[1], lv[1]);
            bsplit(v.z, hv[2], lv[2]); bsplit(v.w, hv[3], lv[3]);
            *(uint2*)&Ch[o] = *(uint2*)hv;
            *(uint2*)&Cl[o] = *(uint2*)lv;
        } else if (OUTMODE == 4) {
            int j0 = n >> 1;
            float g1a = v.x + bias[j0];
            float g2a = v.y + bias[DFF + j0];
            float g1b = v.z + bias[j0 + 1];
            float g2b = v.w + bias[DFF + j0 + 1];
            float ga = gelu_t(g1a) * g2a;
            float gb = gelu_t(g1b) * g2b;
            bf16 h0, l0, h1, l1;
            bsplit(ga, h0, l0); bsplit(gb, h1, l1);
            size_t o = (size_t)m * DFF + j0;
            *(unsigned*)&Ch[o] = pack2(h0, h1);
            *(unsigned*)&Cl[o] = pack2(l0, l1);
        } else {  // OUTMODE == 5
            int e = n & 63;
            float4 p = *(const float4*)&Csm[r * LDC + (c4 ^ 32)];
            {
                float4 bb = *(const float4*)&bias[n];
                v.x += bb.x; v.y += bb.y; v.z += bb.z; v.w += bb.w;
                float4 pb = *(const float4*)&bias[n ^ 32];
                p.x += pb.x; p.y += pb.y; p.z += pb.z; p.w += pb.w;
            }
            int s = m & 2047;
            float4 cs = *(const float4*)&cosT[s * HDD + e];
            float4 sn = *(const float4*)&sinT[s * HDD + e];
            float4 o4;
            if (e < 32) {
                o4.x = v.x * cs.x - p.x * sn.x; o4.y = v.y * cs.y - p.y * sn.y;
                o4.z = v.z * cs.z - p.z * sn.z; o4.w = v.w * cs.w - p.w * sn.w;
            } else {
                o4.x = v.x * cs.x + p.x * sn.x; o4.y = v.y * cs.y + p.y * sn.y;
                o4.z = v.z * cs.z + p.z * sn.z; o4.w = v.w * cs.w + p.w * sn.w;
            }
            o4.x *= scale; o4.y *= scale; o4.z *= scale; o4.w *= scale;
            int b = m >> 11, head = n >> 6;
            size_t o = (((size_t)b * HH + head) * SS + s) * HDD + e;
            bf16 hv[4], lv[4];
            bsplit(o4.x, hv[0], lv[0]); bsplit(o4.y, hv[1], lv[1]);
            bsplit(o4.z, hv[2], lv[2]); bsplit(o4.w, hv[3], lv[3]);
            *(uint2*)&Ch[o] = *(uint2*)hv;
            *(uint2*)&Cl[o] = *(uint2*)lv;
        }
    }
}

// ---------------- tensor-core flash attention v3 ----------------
// Max-free unnormalized softmax (scores bounded ~|S|<60 << 88), O accumulated
// in register fragments across all kc iterations (no rescale), cp.async
// double-buffered K/V prefetch.
#define LDQ 72
#define LDKV 72
#define LDP 72
#define LDSS 68
#define ATT_KV_STAGE (4*64*LDKV)     // 18432 bf16 per stage (Kh,Kl,Vh,Vl)
// bytes: Q 2*128*72*2 + KV 2*18432*2 + P 2*128*72*2 + S 128*68*4 = 182272
#define ATT_SMEM 182272
__global__ __launch_bounds__(256, 1) void attn_tc(
    const bf16* __restrict__ Qh_, const bf16* __restrict__ Ql_,
    const bf16* __restrict__ Kh_, const bf16* __restrict__ Kl_,
    const bf16* __restrict__ Vh_, const bf16* __restrict__ Vl_,
    bf16* __restrict__ Oh_, bf16* __restrict__ Ol_)
{
    extern __shared__ __align__(16) char smraw_[];
    bf16* sQh = (bf16*)smraw_;
    bf16* sQl = sQh + 128 * LDQ;
    bf16* sKV = sQl + 128 * LDQ;              // 2 stages x (Kh|Kl|Vh|Vl)
    bf16* sPh = sKV + 2 * ATT_KV_STAGE;
    bf16* sPl = sPh + 128 * LDP;
    float* sS = (float*)(sPl + 128 * LDP);    // 128 x 68 fp32 (also final O staging)

    int tid = threadIdx.x;
    int warp = tid >> 5;
    int bh = blockIdx.y;
    int q0 = blockIdx.x * 128;
    size_t qoff = ((size_t)bh * SS + q0) * HDD;
    size_t bhoff = (size_t)bh * SS * HDD;

    // load Q tiles (hi/lo) synchronously, once
#pragma unroll
    for (int i = 0; i < 4; i++) {
        int idx = tid + i * 256;
        int r = idx >> 3, c8 = (idx & 7) * 8;
        *(uint4*)&sQh[r * LDQ + c8] = *(const uint4*)&Qh_[qoff + (size_t)r * HDD + c8];
        *(uint4*)&sQl[r * LDQ + c8] = *(const uint4*)&Ql_[qoff + (size_t)r * HDD + c8];
    }

    auto kv_issue = [&](int it, int st) {
        size_t koff = bhoff + (size_t)(it * 64) * HDD;
        bf16* kh = sKV + st * ATT_KV_STAGE;
        bf16* kl = kh + 64 * LDKV;
        bf16* vh = kl + 64 * LDKV;
        bf16* vl = vh + 64 * LDKV;
#pragma unroll
        for (int i = 0; i < 2; i++) {
            int idx = tid + i * 256;
            int rr = idx >> 3, c8 = (idx & 7) * 8;
            size_t g = koff + (size_t)rr * HDD + c8;
            __pipeline_memcpy_async(&kh[rr * LDKV + c8], &Kh_[g], 16);
            __pipeline_memcpy_async(&kl[rr * LDKV + c8], &Kl_[g], 16);
            __pipeline_memcpy_async(&vh[rr * LDKV + c8], &Vh_[g], 16);
            __pipeline_memcpy_async(&vl[rr * LDKV + c8], &Vl_[g], 16);
        }
        __pipeline_commit();
    };

    kv_issue(0, 0);
    kv_issue(1, 1);

    // persistent O accumulators: warp's 16 q-rows x 64 d
    wmma::fragment<wmma::accumulator, 16, 16, 16, float> of[4];
#pragma unroll
    for (int j = 0; j < 4; j++) wmma::fill_fragment(of[j], 0.f);

    float l = 0.f;                       // per-thread partial (2 threads/row)
    int r = tid >> 1, c0 = (tid & 1) * 32;
    const int niter = SS / 64;           // 32

    for (int it = 0; it < niter; it++) {
        int st = it & 1;
        __pipeline_wait_prior(1);
        __syncthreads();
        bf16* kh = sKV + st * ATT_KV_STAGE;
        bf16* kl = kh + 64 * LDKV;
        bf16* vh = kl + 64 * LDKV;
        bf16* vl = vh + 64 * LDKV;

        // ---- S = Qh*Kh + Qh*Kl + Ql*Kh ----
        {
            wmma::fragment<wmma::accumulator, 16, 16, 16, float> sf[4];
#pragma unroll
            for (int j = 0; j < 4; j++) wmma::fill_fragment(sf[j], 0.f);
#pragma unroll
            for (int ks = 0; ks < 4; ks++) {
                wmma::fragment<wmma::matrix_a, 16, 16, 16, bf16, wmma::row_major> ah, al;
                wmma::load_matrix_sync(ah, &sQh[(warp * 16) * LDQ + ks * 16], LDQ);
                wmma::load_matrix_sync(al, &sQl[(warp * 16) * LDQ + ks * 16], LDQ);
#pragma unroll
                for (int j = 0; j < 4; j++) {
                    wmma::fragment<wmma::matrix_b, 16, 16, 16, bf16, wmma::col_major> bhf, blf;
                    wmma::load_matrix_sync(bhf, &kh[(j * 16) * LDKV + ks * 16], LDKV);
                    wmma::load_matrix_sync(blf, &kl[(j * 16) * LDKV + ks * 16], LDKV);
                    wmma::mma_sync(sf[j], ah, bhf, sf[j]);
                    wmma::mma_sync(sf[j], ah, blf, sf[j]);
                    wmma::mma_sync(sf[j], al, bhf, sf[j]);
                }
            }
#pragma unroll
            for (int j = 0; j < 4; j++)
                wmma::store_matrix_sync(&sS[(warp * 16) * LDSS + j * 16], sf[j], LDSS, wmma::mem_row_major);
        }
        __syncthreads();

        // ---- max-free softmax: P = exp(S), l += row partials ----
        {
            const float* srow = sS + r * LDSS + c0;
            unsigned* ph = (unsigned*)&sPh[r * LDP + c0];
            unsigned* pl = (unsigned*)&sPl[r * LDP + c0];
            float sum = 0.f;
#pragma unroll
            for (int cc = 0; cc < 8; cc++) {
                float4 sv = *(const float4*)&srow[cc * 4];
                float p0 = __expf(sv.x), p1 = __expf(sv.y);
                float p2 = __expf(sv.z), p3 = __expf(sv.w);
                sum += (p0 + p1) + (p2 + p3);
                bf16 h0, l0, h1, l1, h2, l2, h3, l3;
                bsplit(p0, h0, l0); bsplit(p1, h1, l1);
                bsplit(p2, h2, l2); bsplit(p3, h3, l3);
                uint2 uh = { pack2(h0, h1), pack2(h2, h3) };
                uint2 ul = { pack2(l0, l1), pack2(l2, l3) };
                *(uint2*)&ph[cc * 2] = uh;
                *(uint2*)&pl[cc * 2] = ul;
            }
            l += sum;
        }
        __syncthreads();

        // ---- of += Ph*Vh + Pl*Vh + Ph*Vl (register accumulation) ----
        {
            wmma::fragment<wmma::matrix_a, 16, 16, 16, bf16, wmma::row_major> pah[4], pal[4];
#pragma unroll
            for (int ks = 0; ks < 4; ks++) {
                wmma::load_matrix_sync(pah[ks], &sPh[(warp * 16) * LDP + ks * 16], LDP);
                wmma::load_matrix_sync(pal[ks], &sPl[(warp * 16) * LDP + ks * 16], LDP);
            }
#pragma unroll
            for (int j = 0; j < 4; j++) {
#pragma unroll
                for (int ks = 0; ks < 4; ks++) {
                    wmma::fragment<wmma::matrix_b, 16, 16, 16, bf16, wmma::row_major> vbh, vbl;
                    wmma::load_matrix_sync(vbh, &vh[(ks * 16) * LDKV + j * 16], LDKV);
                    wmma::load_matrix_sync(vbl, &vl[(ks * 16) * LDKV + j * 16], LDKV);
                    wmma::mma_sync(of[j], pah[ks], vbh, of[j]);
                    wmma::mma_sync(of[j], pal[ks], vbh, of[j]);
                    wmma::mma_sync(of[j], pah[ks], vbl, of[j]);
                }
            }
        }
        __syncthreads();   // stage st KV + P reads done before refill

        if (it + 2 < niter) kv_issue(it + 2, st);
        else __pipeline_commit();
    }

    // ---- finalize: l pair-combine, O -> smem -> global split ----
    l += __shfl_xor_sync(0xffffffffu, l, 1);
#pragma unroll
    for (int j = 0; j < 4; j++)
        wmma::store_matrix_sync(&sS[(warp * 16) * LDSS + j * 16], of[j], LDSS, wmma::mem_row_major);
    __syncthreads();

    int b = bh / HH, hd = bh % HH;
    float inv = 1.0f / l;
    size_t obase = ((size_t)(b * SS + q0 + r)) * DD + hd * HDD + c0;
    const float* orow = sS + r * LDSS + c0;
#pragma unroll
    for (int cc = 0; cc < 8; cc++) {
        float4 ov = *(const float4*)&orow[cc * 4];
        bf16 h0, l0, h1, l1, h2, l2, h3, l3;
        bsplit(ov.x * inv, h0, l0); bsplit(ov.y * inv, h1, l1);
        bsplit(ov.z * inv, h2, l2); bsplit(ov.w * inv, h3, l3);
        uint2 uh = { pack2(h0, h1), pack2(h2, h3) };
        uint2 ul = { pack2(l0, l1), pack2(l2, l3) };
        *(uint2*)&Oh_[obase + cc * 4] = uh;
        *(uint2*)&Ol_[obase + cc * 4] = ul;
    }
}

// ---------------- launch ----------------
extern "C" void kernel_launch(void* const* d_in, const int* in_sizes, int n_in,
                              void* d_out, int out_size) {
    const float* x    = (const float*)d_in[0];
    const float* anw  = (const float*)d_in[1];
    const float* anb  = (const float*)d_in[2];
    const float* Uq   = (const float*)d_in[3];
    const float* Vq   = (const float*)d_in[4];
    const float* bq   = (const float*)d_in[5];
    const float* Uk   = (const float*)d_in[6];
    const float* Vk   = (const float*)d_in[7];
    const float* bk   = (const float*)d_in[8];
    const float* Uv   = (const float*)d_in[9];
    const float* Vv   = (const float*)d_in[10];
    const float* bv   = (const float*)d_in[11];
    const float* Wo_w = (const float*)d_in[12];
    const float* Wo_b = (const float*)d_in[13];
    const float* mnw  = (const float*)d_in[14];
    const float* mnb  = (const float*)d_in[15];
    const float* Ui   = (const float*)d_in[16];
    const float* Vi   = (const float*)d_in[17];
    const float* bi   = (const float*)d_in[18];
    const float* Uo   = (const float*)d_in[19];
    const float* Vo   = (const float*)d_in[20];
    const float* bo   = (const float*)d_in[21];
    const float* cosT = (const float*)d_in[22];
    const float* sinT = (const float*)d_in[23];
    float* out = (float*)d_out;

    bf16 *hh,*hl,*weffh,*weffl,*woth,*wotl,*uih,*uil,*vih,*vil,*uoh,*uol,*voh,*vol;
    bf16 *qh,*ql,*kh,*kl,*vh,*vl,*oh,*ol,*h2h,*h2l,*t1h,*t1l,*gh,*gl,*t2h,*t2l;
    float *x1;
    cudaGetSymbolAddress((void**)&hh, g_hh);   cudaGetSymbolAddress((void**)&hl, g_hl);
    cudaGetSymbolAddress((void**)&weffh, g_weffh); cudaGetSymbolAddress((void**)&weffl, g_weffl);
    cudaGetSymbolAddress((void**)&woth, g_woth);   cudaGetSymbolAddress((void**)&wotl, g_wotl);
    cudaGetSymbolAddress((void**)&uih, g_uih); cudaGetSymbolAddress((void**)&uil, g_uil);
    cudaGetSymbolAddress((void**)&vih, g_vih); cudaGetSymbolAddress((void**)&vil, g_vil);
    cudaGetSymbolAddress((void**)&uoh, g_uoh); cudaGetSymbolAddress((void**)&uol, g_uol);
    cudaGetSymbolAddress((void**)&voh, g_voh); cudaGetSymbolAddress((void**)&vol, g_vol);
    cudaGetSymbolAddress((void**)&qh, g_qh); cudaGetSymbolAddress((void**)&ql, g_ql);
    cudaGetSymbolAddress((void**)&kh, g_kh); cudaGetSymbolAddress((void**)&kl, g_kl);
    cudaGetSymbolAddress((void**)&vh, g_vh); cudaGetSymbolAddress((void**)&vl, g_vl);
    cudaGetSymbolAddress((void**)&oh, g_oh); cudaGetSymbolAddress((void**)&ol, g_ol);
    cudaGetSymbolAddress((void**)&x1, g_x1);
    cudaGetSymbolAddress((void**)&h2h, g_h2h); cudaGetSymbolAddress((void**)&h2l, g_h2l);
    cudaGetSymbolAddress((void**)&t1h, g_t1h); cudaGetSymbolAddress((void**)&t1l, g_t1l);
    cudaGetSymbolAddress((void**)&gh, g_gh); cudaGetSymbolAddress((void**)&gl, g_gl);
    cudaGetSymbolAddress((void**)&t2h, g_t2h); cudaGetSymbolAddress((void**)&t2l, g_t2l);

    cudaFuncSetAttribute(attn_tc, cudaFuncAttributeMaxDynamicSharedMemorySize, ATT_SMEM);
    cudaFuncSetAttribute(gemm_bf3<0>, cudaFuncAttributeMaxDynamicSharedMemorySize, GEMM_SMEM);
    cudaFuncSetAttribute(gemm_bf3<2>, cudaFuncAttributeMaxDynamicSharedMemorySize, GEMM_SMEM);
    cudaFuncSetAttribute(gemm_bf3<3>, cudaFuncAttributeMaxDynamicSharedMemorySize, GEMM_SMEM);
    cudaFuncSetAttribute(gemm_bf3<4>, cudaFuncAttributeMaxDynamicSharedMemorySize, GEMM_SMEM);
    cudaFuncSetAttribute(gemm_bf3<5>, cudaFuncAttributeMaxDynamicSharedMemorySize, GEMM_SMEM);

    // 1. LN1
    ln_split<<<ROWS, 256>>>(x, anw, anb, hh, hl);
    // 2. weights -> hi/lo
    weff_kernel<<<(3 * DD * DD + 255) / 256, 256>>>(Uq, Vq, Uk, Vk, Uv, Vv, weffh, weffl);
    wo_t_split<<<(DD * DD + 255) / 256, 256>>>(Wo_w, woth, wotl);
    split_kernel<<<(DD * RF + 255) / 256, 256>>>(Ui, uih, uil, DD * RF);
    vi_perm_split<<<(RF * 2 * DFF + 255) / 256, 256>>>(Vi, vih, vil);
    split_kernel<<<(DFF * RF + 255) / 256, 256>>>(Uo, uoh, uol, DFF * RF);
    split_kernel<<<(RF * DD + 255) / 256, 256>>>(Vo, voh, vol, RF * DD);
    // 3. Q/K fused rope+scale+split, V scatter+split
    dim3 gQKV(DD / 128, ROWS / 128);
    gemm_bf3<5><<<gQKV, 256, GEMM_SMEM>>>(hh, hl, weffh,           weffl,           bq, nullptr, cosT, sinT, 0.125f, nullptr, qh, ql, ROWS, DD, DD);
    gemm_bf3<5><<<gQKV, 256, GEMM_SMEM>>>(hh, hl, weffh + DD * DD, weffl + DD * DD, bk, nullptr, cosT, sinT, 1.0f,   nullptr, kh, kl, ROWS, DD, DD);
    gemm_bf3<3><<<gQKV, 256, GEMM_SMEM>>>(hh, hl, weffh + 2*DD*DD, weffl + 2*DD*DD, bv, nullptr, nullptr, nullptr, 1.f, nullptr, vh, vl, ROWS, DD, DD);
    // 4. tensor-core attention (max-free flash)
    attn_tc<<<dim3(SS / 128, BB * HH), 256, ATT_SMEM>>>(qh, ql, kh, kl, vh, vl, oh, ol);
    // 5. x1 = x + o @ Wo^T + Wo_b
    gemm_bf3<0><<<dim3(DD / 128, ROWS / 128), 256, GEMM_SMEM>>>(oh, ol, woth, wotl, Wo_b, x, nullptr, nullptr, 1.f, x1, nullptr, nullptr, ROWS, DD, DD);
    // 6. LN2
    ln_split<<<ROWS, 256>>>(x1, mnw, mnb, h2h, h2l);
    // 7. t1 = h2 @ Ui
    gemm_bf3<2><<<dim3(RF / 128, ROWS / 128), 256, GEMM_SMEM>>>(h2h, h2l, uih, uil, nullptr, nullptr, nullptr, nullptr, 1.f, nullptr, t1h, t1l, ROWS, RF, DD);
    // 8. g = GEGLU(t1 @ ViP + biP) fused
    gemm_bf3<4><<<dim3(2 * DFF / 128, ROWS / 128), 256, GEMM_SMEM>>>(t1h, t1l, vih, vil, bi, nullptr, nullptr, nullptr, 1.f, nullptr, gh, gl, ROWS, 2 * DFF, RF);
    // 9. t2 = g @ Uo
    gemm_bf3<2><<<dim3(RF / 128, ROWS / 128), 256, GEMM_SMEM>>>(gh, gl, uoh, uol, nullptr, nullptr, nullptr, nullptr, 1.f, nullptr, t2h, t2l, ROWS, RF, DFF);
    // 10. out = x1 + t2 @ Vo + bo
    gemm_bf3<0><<<dim3(DD / 128, ROWS / 128), 256, GEMM_SMEM>>>(t2h, t2l, voh, vol, bo, x1, nullptr, nullptr, 1.f, out, nullptr, nullptr, ROWS, DD, RF);
}